// round 6
// baseline (speedup 1.0000x reference)
#include <cuda_runtime.h>
#include <cuda_bf16.h>
#include <cstdint>

#define N_ROWS 8192
#define D_DIM  768
#define W_DIM  24576
#define K_TOP  64
#define NCAP   256     // candidate capacity
#define NSORT  256
#define THR_SLACK 8u   // bf16-key ulps of threshold slack

// ---------------- scratch (device globals) ---------------------------------
__device__ __align__(16) __nv_bfloat16 g_xb [(size_t)N_ROWS * D_DIM];
__device__ __align__(16) __nv_bfloat16 g_aeb[(size_t)W_DIM * D_DIM];
__device__ __align__(16) __nv_bfloat16 g_preb[(size_t)N_ROWS * W_DIM];   // 402 MB
__device__ __align__(16) float g_AdT[(size_t)W_DIM * D_DIM];             // 75 MB
__device__ float g_beff[W_DIM];
__device__ int   g_cand[(size_t)N_ROWS * NCAP];
__device__ int   g_candcnt[N_ROWS];
__device__ float g_vals[N_ROWS * K_TOP];
__device__ int   g_idx [N_ROWS * K_TOP];

// ---------------- helpers ----------------------------------------------------
__device__ __forceinline__ uint32_t smem_u32(const void* p) {
    uint32_t a;
    asm("{ .reg .u64 t; cvta.to.shared.u64 t, %1; cvt.u32.u64 %0, t; }"
        : "=r"(a) : "l"(p));
    return a;
}
#define CP16(sa, g) asm volatile("cp.async.cg.shared.global [%0], [%1], 16;" :: "r"(sa), "l"(g))
#define CP_COMMIT() asm volatile("cp.async.commit_group;" ::: "memory")
#define CP_WAIT1()  asm volatile("cp.async.wait_group 1;" ::: "memory")

#define LDSM4(r0, r1, r2, r3, a) \
    asm volatile("ldmatrix.sync.aligned.m8n8.x4.shared.b16 {%0,%1,%2,%3}, [%4];" \
                 : "=r"(r0), "=r"(r1), "=r"(r2), "=r"(r3) : "r"(a))

__device__ __forceinline__ void mma16816(float* c, const uint32_t* a, const uint32_t* b) {
    asm volatile("mma.sync.aligned.m16n8k16.row.col.f32.bf16.bf16.f32 "
                 "{%0,%1,%2,%3}, {%4,%5,%6,%7}, {%8,%9}, {%0,%1,%2,%3};"
                 : "+f"(c[0]), "+f"(c[1]), "+f"(c[2]), "+f"(c[3])
                 : "r"(a[0]), "r"(a[1]), "r"(a[2]), "r"(a[3]), "r"(b[0]), "r"(b[1]));
}

// ---------------- fp32 -> bf16 convert --------------------------------------
__global__ __launch_bounds__(256) void cvt_kernel(const float* __restrict__ src,
                                                  __nv_bfloat16* __restrict__ dst, int n4) {
    int i = blockIdx.x * 256 + threadIdx.x;
    if (i >= n4) return;
    float4 v = ((const float4*)src)[i];
    uint32_t p0, p1;
    asm("cvt.rn.bf16x2.f32 %0, %1, %2;" : "=r"(p0) : "f"(v.y), "f"(v.x));
    asm("cvt.rn.bf16x2.f32 %0, %1, %2;" : "=r"(p1) : "f"(v.w), "f"(v.z));
    ((uint2*)dst)[i] = make_uint2(p0, p1);
}

// ---------------- beff[w] = be[w] - dot(bd, Ae[w,:]) ------------------------
__global__ __launch_bounds__(256) void beff_kernel(const float* __restrict__ be,
                                                   const float* __restrict__ bd,
                                                   const float* __restrict__ Ae) {
    int w    = blockIdx.x * 8 + (threadIdx.x >> 5);
    int lane = threadIdx.x & 31;
    const float* row = Ae + (size_t)w * D_DIM;
    float s = 0.f;
    for (int d = lane; d < D_DIM; d += 32) s += bd[d] * row[d];
    #pragma unroll
    for (int o = 16; o > 0; o >>= 1) s += __shfl_down_sync(0xffffffffu, s, o);
    if (lane == 0) g_beff[w] = be[w] - s;
}

// ---------------- AdT[w,d] = Ad[d,w]  (half of D per launch) -----------------
__global__ __launch_bounds__(256) void transpose_kernel(const float* __restrict__ Ad,
                                                        int d_base) {
    __shared__ float tile[32][33];
    int w0 = blockIdx.x * 32;
    int d0 = d_base + blockIdx.y * 32;
    int tx = threadIdx.x, ty = threadIdx.y;   // 32 x 8
    #pragma unroll
    for (int i = 0; i < 32; i += 8)
        tile[ty + i][tx] = Ad[(size_t)(d0 + ty + i) * W_DIM + w0 + tx];
    __syncthreads();
    #pragma unroll
    for (int i = 0; i < 32; i += 8)
        g_AdT[(size_t)(w0 + ty + i) * D_DIM + d0 + tx] = tile[tx][ty + i];
}

// ---------------- bf16 HMMA GEMM: preb = Xb @ Aeb^T + beff -------------------
// CTA tile 128x256, BK=32, 3-stage cp.async, 8 warps, warp tile 64x64.
#define GBK     32
#define NSTAGE  3
#define ROWPITCH 80                       // 64B data + 16B pad
#define ASTG    (128 * ROWPITCH)          // 10240
#define BSTG    (256 * ROWPITCH)          // 20480
#define STAGEB  (ASTG + BSTG)             // 30720
#define KT      (D_DIM / GBK)             // 24

__global__ __launch_bounds__(256, 1) void gemm_kernel() {
    extern __shared__ char smem[];
    const uint32_t SB = (smem_u32(smem) + 127u) & ~127u;
    const int tid  = threadIdx.x;
    const int wid  = tid >> 5;
    const int lane = tid & 31;
    const int wm   = wid & 1;              // 2 warp rows (64 each)
    const int wn   = wid >> 1;             // 4 warp cols (64 each)

    const __nv_bfloat16* Ag = g_xb  + (size_t)(blockIdx.y * 128) * D_DIM;
    const __nv_bfloat16* Bg = g_aeb + (size_t)(blockIdx.x * 256) * D_DIM;

    // 1536 cp16 per stage (A 512, B 1024) -> 6 per thread
    auto load_stage = [&](int s, int k0) {
        const uint32_t ab = SB + s * STAGEB;
        const uint32_t bb = ab + ASTG;
        #pragma unroll
        for (int o = 0; o < 6; ++o) {
            int flat = tid + o * 256;
            if (flat < 512) {
                int r = flat >> 2, c4 = flat & 3;
                CP16(ab + r * ROWPITCH + c4 * 16, Ag + (size_t)r * D_DIM + k0 + c4 * 8);
            } else {
                int q = flat - 512;
                int r = q >> 2, c4 = q & 3;
                CP16(bb + r * ROWPITCH + c4 * 16, Bg + (size_t)r * D_DIM + k0 + c4 * 8);
            }
        }
    };

    float acc[4][8][4];
    #pragma unroll
    for (int i = 0; i < 4; ++i)
        #pragma unroll
        for (int j = 0; j < 8; ++j)
            #pragma unroll
            for (int q = 0; q < 4; ++q) acc[i][j][q] = 0.f;

    load_stage(0, 0);  CP_COMMIT();
    load_stage(1, 32); CP_COMMIT();

    const int a_row = (lane & 15);
    const int a_kb  = (lane >> 4) * 16;
    const int b_row = ((lane >> 4) & 1) * 8 + (lane & 7);
    const int b_kb  = ((lane >> 3) & 1) * 16;

    for (int it = 0; it < KT; ++it) {
        CP_WAIT1();
        __syncthreads();
        {
            int nx = it + 2;
            if (nx < KT) load_stage(nx % 3, nx * GBK);
            CP_COMMIT();
        }

        const uint32_t ab = SB + (it % 3) * STAGEB;
        const uint32_t bb = ab + ASTG;
        #pragma unroll
        for (int ks = 0; ks < 2; ++ks) {
            uint32_t af[4][4], bf[4][4];
            #pragma unroll
            for (int mt = 0; mt < 4; ++mt) {
                uint32_t addr = ab + (wm * 64 + mt * 16 + a_row) * ROWPITCH
                              + a_kb + ks * 32;
                LDSM4(af[mt][0], af[mt][1], af[mt][2], af[mt][3], addr);
            }
            #pragma unroll
            for (int bt = 0; bt < 4; ++bt) {
                uint32_t addr = bb + (wn * 64 + bt * 16 + b_row) * ROWPITCH
                              + b_kb + ks * 32;
                LDSM4(bf[bt][0], bf[bt][1], bf[bt][2], bf[bt][3], addr);
            }
            #pragma unroll
            for (int mt = 0; mt < 4; ++mt)
                #pragma unroll
                for (int nt = 0; nt < 8; ++nt)
                    mma16816(acc[mt][nt], af[mt], &bf[nt >> 1][(nt & 1) * 2]);
        }
        __syncthreads();
    }

    // epilogue: add beff, pack bf16x2, store
    const int g  = lane >> 2;
    const int tg = lane & 3;
    const int rowBase = blockIdx.y * 128 + wm * 64;
    const int colBase = blockIdx.x * 256 + wn * 64;
    #pragma unroll
    for (int nt = 0; nt < 8; ++nt) {
        const int c = colBase + nt * 8 + tg * 2;
        const float bz0 = g_beff[c], bz1 = g_beff[c + 1];
        #pragma unroll
        for (int mt = 0; mt < 4; ++mt) {
            const int r0 = rowBase + mt * 16 + g;
            uint32_t p0, p1;
            float v00 = acc[mt][nt][0] + bz0, v01 = acc[mt][nt][1] + bz1;
            float v10 = acc[mt][nt][2] + bz0, v11 = acc[mt][nt][3] + bz1;
            asm("cvt.rn.bf16x2.f32 %0, %1, %2;" : "=r"(p0) : "f"(v01), "f"(v00));
            asm("cvt.rn.bf16x2.f32 %0, %1, %2;" : "=r"(p1) : "f"(v11), "f"(v10));
            *(uint32_t*)(g_preb + (size_t)r0 * W_DIM + c)       = p0;
            *(uint32_t*)(g_preb + (size_t)(r0 + 8) * W_DIM + c) = p1;
        }
    }
}

// ---------------- per-row candidate select (bf16 keys, slack threshold) -----
__global__ __launch_bounds__(256) void topk_kernel() {
    extern __shared__ uint16_t sk[];          // W_DIM keys (48KB)
    __shared__ uint32_t hist[256];
    __shared__ uint32_t s_b1, s_need, s_thr, s_cnt;

    const int tid = threadIdx.x;
    const int row = blockIdx.x;
    const uint4* src = (const uint4*)(g_preb + (size_t)row * W_DIM);

    hist[tid] = 0u;
    if (tid == 0) s_cnt = 0u;
    __syncthreads();

    // fused: convert to order-preserving u16 keys + level-1 histogram (high byte)
    for (int i = tid; i < W_DIM / 8; i += 256) {
        uint4 v = src[i];
        uint32_t w[4] = {v.x, v.y, v.z, v.w};
        #pragma unroll
        for (int q = 0; q < 4; ++q) {
            uint16_t lo = (uint16_t)(w[q] & 0xFFFF), hi = (uint16_t)(w[q] >> 16);
            uint16_t k0 = (lo & 0x8000) ? (uint16_t)~lo : (uint16_t)(lo | 0x8000);
            uint16_t k1 = (hi & 0x8000) ? (uint16_t)~hi : (uint16_t)(hi | 0x8000);
            sk[i * 8 + q * 2 + 0] = k0;
            sk[i * 8 + q * 2 + 1] = k1;
            int bin0 = k0 >> 8;
            unsigned m0 = __match_any_sync(0xffffffffu, bin0);
            if ((tid & 31) == (__ffs(m0) - 1)) atomicAdd(&hist[bin0], (uint32_t)__popc(m0));
            int bin1 = k1 >> 8;
            unsigned m1 = __match_any_sync(0xffffffffu, bin1);
            if ((tid & 31) == (__ffs(m1) - 1)) atomicAdd(&hist[bin1], (uint32_t)__popc(m1));
        }
    }
    __syncthreads();
    if (tid == 0) {
        uint32_t cum = 0u; int b1 = 0;
        for (int b = 255; b >= 0; --b) {
            if (cum + hist[b] >= 128u) { b1 = b; break; }
            cum += hist[b];
        }
        s_b1 = (uint32_t)b1; s_need = 128u - cum;
    }
    __syncthreads();
    const uint32_t b1 = s_b1;
    hist[tid] = 0u;
    __syncthreads();

    // level 2: low byte within bin b1
    for (int i = tid; i < W_DIM; i += 256) {
        uint16_t u = sk[i];
        int bin = ((u >> 8) == b1) ? (int)(u & 0xFF) : -1;
        unsigned m = __match_any_sync(0xffffffffu, bin);
        if (bin >= 0 && (tid & 31) == (__ffs(m) - 1))
            atomicAdd(&hist[bin], (uint32_t)__popc(m));
    }
    __syncthreads();
    if (tid == 0) {
        uint32_t need = s_need, cum = 0u; int b2 = 0;
        for (int b = 255; b >= 0; --b) {
            if (cum + hist[b] >= need) { b2 = b; break; }
            cum += hist[b];
        }
        uint32_t thr = (b1 << 8) | (uint32_t)b2;
        s_thr = (thr > THR_SLACK) ? thr - THR_SLACK : 0u;
    }
    __syncthreads();
    const uint32_t thr = s_thr;
    int* crow = g_cand + (size_t)row * NCAP;

    for (int i = tid; i < W_DIM; i += 256) {
        if ((uint32_t)sk[i] >= thr) {
            int pos = (int)atomicAdd(&s_cnt, 1u);
            if (pos < NCAP) crow[pos] = i;
        }
    }
    __syncthreads();
    if (tid == 0) g_candcnt[row] = (s_cnt < NCAP) ? (int)s_cnt : NCAP;
}

// ---------------- exact fp32 rescore: ONE THREAD PER CANDIDATE --------------
// FROZEN accumulation order: ascending-k scalar fmaf chain (matches reference).
__global__ __launch_bounds__(256) void rescore_kernel(const float* __restrict__ x,
                                                      const float* __restrict__ Ae) {
    __shared__ __align__(16) float sx[D_DIM];
    __shared__ unsigned long long skey[NSORT];

    const int tid = threadIdx.x, row = blockIdx.x;
    const int cnt = g_candcnt[row];
    for (int i = tid; i < D_DIM / 4; i += 256)
        ((float4*)sx)[i] = ((const float4*)(x + (size_t)row * D_DIM))[i];
    skey[tid] = 0ull;
    __syncthreads();

    if (tid < cnt) {
        const int c = g_cand[(size_t)row * NCAP + tid];
        const float4* ar = (const float4*)(Ae + (size_t)c * D_DIM);
        const float4* xr = (const float4*)sx;
        float acc = 0.f;
        #pragma unroll 4
        for (int q = 0; q < D_DIM / 4; ++q) {        // ascending k, scalar chain
            float4 a = ar[q], b = xr[q];
            acc = fmaf(a.x, b.x, acc);
            acc = fmaf(a.y, b.y, acc);
            acc = fmaf(a.z, b.z, acc);
            acc = fmaf(a.w, b.w, acc);
        }
        float v = acc + g_beff[c];
        uint32_t bbits = __float_as_uint(v);
        uint32_t fk = (bbits & 0x80000000u) ? ~bbits : (bbits | 0x80000000u);
        skey[tid] = ((unsigned long long)fk << 32) | (uint32_t)(~(uint32_t)c);
    }
    __syncthreads();

    // bitonic sort (desc by val, ties: smaller idx first)
    for (int k = 2; k <= NSORT; k <<= 1) {
        for (int jj = k >> 1; jj > 0; jj >>= 1) {
            int p = tid ^ jj;
            if (p > tid) {
                bool up = ((tid & k) == 0);
                unsigned long long a = skey[tid], b = skey[p];
                bool sw = up ? (a < b) : (a > b);
                if (sw) { skey[tid] = b; skey[p] = a; }
            }
            __syncthreads();
        }
    }
    if (tid < K_TOP) {
        unsigned long long kk = skey[tid];
        uint32_t fk = (uint32_t)(kk >> 32);
        uint32_t b  = (fk & 0x80000000u) ? (fk ^ 0x80000000u) : ~fk;
        g_vals[row * K_TOP + tid] = fmaxf(__uint_as_float(b), 0.f);
        g_idx [row * K_TOP + tid] = (int)(~(uint32_t)kk);
    }
}

// ---------------- decode: out[n,:] = sum_j v_j * AdT[i_j,:] + bd -------------
__global__ __launch_bounds__(256) void decode_kernel(const float* __restrict__ bd,
                                                     float* __restrict__ out) {
    __shared__ float         sv[K_TOP];
    __shared__ const float4* sp[K_TOP];
    const int row = blockIdx.x;
    const int tid = threadIdx.x;
    if (tid < K_TOP) {
        sv[tid] = g_vals[row * K_TOP + tid];
        sp[tid] = (const float4*)(g_AdT + (size_t)g_idx[row * K_TOP + tid] * D_DIM);
    }
    __syncthreads();
    if (tid < D_DIM / 4) {
        float4 acc = ((const float4*)bd)[tid];
        #pragma unroll 8
        for (int j = 0; j < K_TOP; ++j) {
            float4 a = sp[j][tid];
            float  v = sv[j];
            acc.x = fmaf(v, a.x, acc.x);
            acc.y = fmaf(v, a.y, acc.y);
            acc.z = fmaf(v, a.z, acc.z);
            acc.w = fmaf(v, a.w, acc.w);
        }
        ((float4*)(out + (size_t)row * D_DIM))[tid] = acc;
    }
}

// ---------------- launch -----------------------------------------------------
extern "C" void kernel_launch(void* const* d_in, const int* in_sizes, int n_in,
                              void* d_out, int out_size) {
    const float* x  = (const float*)d_in[0];
    const float* Ae = (const float*)d_in[1];
    const float* be = (const float*)d_in[2];
    const float* Ad = (const float*)d_in[3];
    const float* bd = (const float*)d_in[4];
    float* out = (float*)d_out;

    __nv_bfloat16 *xb_p, *aeb_p;
    cudaGetSymbolAddress((void**)&xb_p,  g_xb);
    cudaGetSymbolAddress((void**)&aeb_p, g_aeb);

    const int gemm_smem = NSTAGE * STAGEB + 256;      // ~92.4 KB
    cudaFuncSetAttribute(gemm_kernel, cudaFuncAttributeMaxDynamicSharedMemorySize, gemm_smem);
    const int topk_smem = W_DIM * (int)sizeof(uint16_t);   // 48 KB
    cudaFuncSetAttribute(topk_kernel, cudaFuncAttributeMaxDynamicSharedMemorySize, topk_smem);

    cvt_kernel<<<(N_ROWS * D_DIM / 4 + 255) / 256, 256>>>(x,  xb_p,  N_ROWS * D_DIM / 4);
    cvt_kernel<<<(W_DIM * D_DIM / 4 + 255) / 256, 256>>>(Ae, aeb_p, W_DIM * D_DIM / 4);
    beff_kernel     <<<W_DIM / 8, 256>>>(be, bd, Ae);
    transpose_kernel<<<dim3(W_DIM / 32, D_DIM / 64), dim3(32, 8)>>>(Ad, 0);
    transpose_kernel<<<dim3(W_DIM / 32, D_DIM / 64), dim3(32, 8)>>>(Ad, D_DIM / 2);
    gemm_kernel     <<<dim3(W_DIM / 256, N_ROWS / 128), 256, gemm_smem>>>();
    topk_kernel     <<<N_ROWS, 256, topk_smem>>>();
    rescore_kernel  <<<N_ROWS, 256>>>(x, Ae);
    decode_kernel   <<<N_ROWS, 256>>>(bd, out);
}

// round 7
// speedup vs baseline: 1.0721x; 1.0721x over previous
#include <cuda_runtime.h>
#include <cuda_bf16.h>
#include <cstdint>

#define N_ROWS 8192
#define D_DIM  768
#define W_DIM  24576
#define K_TOP  64
#define NCAP   256     // candidate capacity
#define NSORT  256
#define THR_SLACK 8u   // bf16-key ulps of threshold slack

// ---------------- scratch (device globals) ---------------------------------
__device__ __align__(16) __nv_bfloat16 g_xb [(size_t)N_ROWS * D_DIM];
__device__ __align__(16) __nv_bfloat16 g_aeb[(size_t)W_DIM * D_DIM];
__device__ __align__(16) __nv_bfloat16 g_preb[(size_t)N_ROWS * W_DIM];   // 402 MB
__device__ __align__(16) float g_AdT[(size_t)W_DIM * D_DIM];             // 75 MB
__device__ float g_beff[W_DIM];
__device__ int   g_cand[(size_t)N_ROWS * NCAP];
__device__ int   g_candcnt[N_ROWS];
__device__ float g_vals[N_ROWS * K_TOP];
__device__ int   g_idx [N_ROWS * K_TOP];

// ---------------- helpers ----------------------------------------------------
__device__ __forceinline__ uint32_t smem_u32(const void* p) {
    uint32_t a;
    asm("{ .reg .u64 t; cvta.to.shared.u64 t, %1; cvt.u32.u64 %0, t; }"
        : "=r"(a) : "l"(p));
    return a;
}
#define CP16(sa, g) asm volatile("cp.async.cg.shared.global [%0], [%1], 16;" :: "r"(sa), "l"(g))
#define CP_COMMIT() asm volatile("cp.async.commit_group;" ::: "memory")
#define CP_WAIT2()  asm volatile("cp.async.wait_group 2;" ::: "memory")

#define LDSM4(r0, r1, r2, r3, a) \
    asm volatile("ldmatrix.sync.aligned.m8n8.x4.shared.b16 {%0,%1,%2,%3}, [%4];" \
                 : "=r"(r0), "=r"(r1), "=r"(r2), "=r"(r3) : "r"(a))

__device__ __forceinline__ void mma16816(float* c, const uint32_t* a, const uint32_t* b) {
    asm volatile("mma.sync.aligned.m16n8k16.row.col.f32.bf16.bf16.f32 "
                 "{%0,%1,%2,%3}, {%4,%5,%6,%7}, {%8,%9}, {%0,%1,%2,%3};"
                 : "+f"(c[0]), "+f"(c[1]), "+f"(c[2]), "+f"(c[3])
                 : "r"(a[0]), "r"(a[1]), "r"(a[2]), "r"(a[3]), "r"(b[0]), "r"(b[1]));
}

// ---------------- fp32 -> bf16 convert --------------------------------------
__global__ __launch_bounds__(256) void cvt_kernel(const float* __restrict__ src,
                                                  __nv_bfloat16* __restrict__ dst, int n4) {
    int i = blockIdx.x * 256 + threadIdx.x;
    if (i >= n4) return;
    float4 v = ((const float4*)src)[i];
    uint32_t p0, p1;
    asm("cvt.rn.bf16x2.f32 %0, %1, %2;" : "=r"(p0) : "f"(v.y), "f"(v.x));
    asm("cvt.rn.bf16x2.f32 %0, %1, %2;" : "=r"(p1) : "f"(v.w), "f"(v.z));
    ((uint2*)dst)[i] = make_uint2(p0, p1);
}

// ---------------- beff[w] = be[w] - dot(bd, Ae[w,:]) ------------------------
__global__ __launch_bounds__(256) void beff_kernel(const float* __restrict__ be,
                                                   const float* __restrict__ bd,
                                                   const float* __restrict__ Ae) {
    int w    = blockIdx.x * 8 + (threadIdx.x >> 5);
    int lane = threadIdx.x & 31;
    const float* row = Ae + (size_t)w * D_DIM;
    float s = 0.f;
    for (int d = lane; d < D_DIM; d += 32) s += bd[d] * row[d];
    #pragma unroll
    for (int o = 16; o > 0; o >>= 1) s += __shfl_down_sync(0xffffffffu, s, o);
    if (lane == 0) g_beff[w] = be[w] - s;
}

// ---------------- AdT[w,d] = Ad[d,w]  (half of D per launch) -----------------
__global__ __launch_bounds__(256) void transpose_kernel(const float* __restrict__ Ad,
                                                        int d_base) {
    __shared__ float tile[32][33];
    int w0 = blockIdx.x * 32;
    int d0 = d_base + blockIdx.y * 32;
    int tx = threadIdx.x, ty = threadIdx.y;   // 32 x 8
    #pragma unroll
    for (int i = 0; i < 32; i += 8)
        tile[ty + i][tx] = Ad[(size_t)(d0 + ty + i) * W_DIM + w0 + tx];
    __syncthreads();
    #pragma unroll
    for (int i = 0; i < 32; i += 8)
        g_AdT[(size_t)(w0 + ty + i) * D_DIM + d0 + tx] = tile[tx][ty + i];
}

// ---------------- bf16 HMMA GEMM: preb = Xb @ Aeb^T + beff -------------------
// R5 config (best): CTA tile 128x128, BK=32, 4-stage cp.async, 8 warps (2x4),
// warp tile 64x32, 2 CTAs/SM.
#define GBK     32
#define NSTAGE  4
#define ROWPITCH 80                       // 64B data + 16B pad
#define ASTAGE  (128 * ROWPITCH)
#define STAGEB  (2 * ASTAGE)
#define KT      (D_DIM / GBK)             // 24

__global__ __launch_bounds__(256, 2) void gemm_kernel() {
    extern __shared__ char smem[];
    const uint32_t SB = (smem_u32(smem) + 127u) & ~127u;
    const int tid  = threadIdx.x;
    const int wid  = tid >> 5;
    const int lane = tid & 31;
    const int wm   = wid & 1;
    const int wn   = wid >> 1;

    const __nv_bfloat16* Ag = g_xb  + (size_t)(blockIdx.y * 128) * D_DIM;
    const __nv_bfloat16* Bg = g_aeb + (size_t)(blockIdx.x * 128) * D_DIM;

    const int lrow = tid >> 2;
    const int lcol = tid & 3;

    auto load_stage = [&](int s, int k0) {
        const uint32_t ab = SB + s * STAGEB;
        const uint32_t bb = ab + ASTAGE;
        #pragma unroll
        for (int h = 0; h < 2; ++h) {
            int r = lrow + h * 64;
            CP16(ab + r * ROWPITCH + lcol * 16, Ag + (size_t)r * D_DIM + k0 + lcol * 8);
            CP16(bb + r * ROWPITCH + lcol * 16, Bg + (size_t)r * D_DIM + k0 + lcol * 8);
        }
    };

    float acc[4][4][4];
    #pragma unroll
    for (int i = 0; i < 4; ++i)
        #pragma unroll
        for (int j = 0; j < 4; ++j)
            #pragma unroll
            for (int q = 0; q < 4; ++q) acc[i][j][q] = 0.f;

    load_stage(0, 0);  CP_COMMIT();
    load_stage(1, 32); CP_COMMIT();
    load_stage(2, 64); CP_COMMIT();

    const int a_row = (lane & 15);
    const int a_kb  = (lane >> 4) * 16;
    const int b_row = ((lane >> 4) & 1) * 8 + (lane & 7);
    const int b_kb  = ((lane >> 3) & 1) * 16;

    for (int it = 0; it < KT; ++it) {
        CP_WAIT2();
        __syncthreads();
        if (it + 3 < KT) load_stage((it + 3) & 3, (it + 3) * GBK);
        CP_COMMIT();

        const uint32_t ab = SB + (it & 3) * STAGEB;
        const uint32_t bb = ab + ASTAGE;
        #pragma unroll
        for (int ks = 0; ks < 2; ++ks) {
            uint32_t af[4][4], bf[2][4];
            #pragma unroll
            for (int mt = 0; mt < 4; ++mt) {
                uint32_t addr = ab + (wm * 64 + mt * 16 + a_row) * ROWPITCH
                              + a_kb + ks * 32;
                LDSM4(af[mt][0], af[mt][1], af[mt][2], af[mt][3], addr);
            }
            #pragma unroll
            for (int bt = 0; bt < 2; ++bt) {
                uint32_t addr = bb + (wn * 32 + bt * 16 + b_row) * ROWPITCH
                              + b_kb + ks * 32;
                LDSM4(bf[bt][0], bf[bt][1], bf[bt][2], bf[bt][3], addr);
            }
            #pragma unroll
            for (int mt = 0; mt < 4; ++mt)
                #pragma unroll
                for (int nt = 0; nt < 4; ++nt)
                    mma16816(acc[mt][nt], af[mt], &bf[nt >> 1][(nt & 1) * 2]);
        }
        __syncthreads();
    }

    const int g  = lane >> 2;
    const int tg = lane & 3;
    const int rowBase = blockIdx.y * 128 + wm * 64;
    const int colBase = blockIdx.x * 128 + wn * 32;
    #pragma unroll
    for (int nt = 0; nt < 4; ++nt) {
        const int c = colBase + nt * 8 + tg * 2;
        const float bz0 = g_beff[c], bz1 = g_beff[c + 1];
        #pragma unroll
        for (int mt = 0; mt < 4; ++mt) {
            const int r0 = rowBase + mt * 16 + g;
            uint32_t p0, p1;
            float v00 = acc[mt][nt][0] + bz0, v01 = acc[mt][nt][1] + bz1;
            float v10 = acc[mt][nt][2] + bz0, v11 = acc[mt][nt][3] + bz1;
            asm("cvt.rn.bf16x2.f32 %0, %1, %2;" : "=r"(p0) : "f"(v01), "f"(v00));
            asm("cvt.rn.bf16x2.f32 %0, %1, %2;" : "=r"(p1) : "f"(v11), "f"(v10));
            *(uint32_t*)(g_preb + (size_t)r0 * W_DIM + c)       = p0;
            *(uint32_t*)(g_preb + (size_t)(r0 + 8) * W_DIM + c) = p1;
        }
    }
}

// ---------------- per-row candidate select (bf16 keys, slack threshold) -----
__global__ __launch_bounds__(256) void topk_kernel() {
    extern __shared__ uint16_t sk[];          // W_DIM keys (48KB)
    __shared__ uint32_t hist[256];
    __shared__ uint32_t s_b1, s_need, s_thr, s_cnt;

    const int tid = threadIdx.x;
    const int row = blockIdx.x;
    const uint4* src = (const uint4*)(g_preb + (size_t)row * W_DIM);

    hist[tid] = 0u;
    if (tid == 0) s_cnt = 0u;
    __syncthreads();

    // fused: convert to order-preserving u16 keys + level-1 histogram (high byte)
    for (int i = tid; i < W_DIM / 8; i += 256) {
        uint4 v = src[i];
        uint32_t w[4] = {v.x, v.y, v.z, v.w};
        #pragma unroll
        for (int q = 0; q < 4; ++q) {
            uint16_t lo = (uint16_t)(w[q] & 0xFFFF), hi = (uint16_t)(w[q] >> 16);
            uint16_t k0 = (lo & 0x8000) ? (uint16_t)~lo : (uint16_t)(lo | 0x8000);
            uint16_t k1 = (hi & 0x8000) ? (uint16_t)~hi : (uint16_t)(hi | 0x8000);
            sk[i * 8 + q * 2 + 0] = k0;
            sk[i * 8 + q * 2 + 1] = k1;
            int bin0 = k0 >> 8;
            unsigned m0 = __match_any_sync(0xffffffffu, bin0);
            if ((tid & 31) == (__ffs(m0) - 1)) atomicAdd(&hist[bin0], (uint32_t)__popc(m0));
            int bin1 = k1 >> 8;
            unsigned m1 = __match_any_sync(0xffffffffu, bin1);
            if ((tid & 31) == (__ffs(m1) - 1)) atomicAdd(&hist[bin1], (uint32_t)__popc(m1));
        }
    }
    __syncthreads();
    if (tid == 0) {
        uint32_t cum = 0u; int b1 = 0;
        for (int b = 255; b >= 0; --b) {
            if (cum + hist[b] >= 128u) { b1 = b; break; }
            cum += hist[b];
        }
        s_b1 = (uint32_t)b1; s_need = 128u - cum;
    }
    __syncthreads();
    const uint32_t b1 = s_b1;
    hist[tid] = 0u;
    __syncthreads();

    // level 2: low byte within bin b1
    for (int i = tid; i < W_DIM; i += 256) {
        uint16_t u = sk[i];
        int bin = ((u >> 8) == b1) ? (int)(u & 0xFF) : -1;
        unsigned m = __match_any_sync(0xffffffffu, bin);
        if (bin >= 0 && (tid & 31) == (__ffs(m) - 1))
            atomicAdd(&hist[bin], (uint32_t)__popc(m));
    }
    __syncthreads();
    if (tid == 0) {
        uint32_t need = s_need, cum = 0u; int b2 = 0;
        for (int b = 255; b >= 0; --b) {
            if (cum + hist[b] >= need) { b2 = b; break; }
            cum += hist[b];
        }
        uint32_t thr = (b1 << 8) | (uint32_t)b2;
        s_thr = (thr > THR_SLACK) ? thr - THR_SLACK : 0u;
    }
    __syncthreads();
    const uint32_t thr = s_thr;
    int* crow = g_cand + (size_t)row * NCAP;

    for (int i = tid; i < W_DIM; i += 256) {
        if ((uint32_t)sk[i] >= thr) {
            int pos = (int)atomicAdd(&s_cnt, 1u);
            if (pos < NCAP) crow[pos] = i;
        }
    }
    __syncthreads();
    if (tid == 0) g_candcnt[row] = (s_cnt < NCAP) ? (int)s_cnt : NCAP;
}

// ---------------- exact fp32 rescore: ONE THREAD PER CANDIDATE --------------
// FROZEN accumulation order: ascending-k scalar fmaf chain (matches reference).
__global__ __launch_bounds__(256) void rescore_kernel(const float* __restrict__ x,
                                                      const float* __restrict__ Ae) {
    __shared__ __align__(16) float sx[D_DIM];
    __shared__ unsigned long long skey[NSORT];

    const int tid = threadIdx.x, row = blockIdx.x;
    const int cnt = g_candcnt[row];
    for (int i = tid; i < D_DIM / 4; i += 256)
        ((float4*)sx)[i] = ((const float4*)(x + (size_t)row * D_DIM))[i];
    skey[tid] = 0ull;
    __syncthreads();

    if (tid < cnt) {
        const int c = g_cand[(size_t)row * NCAP + tid];
        const float4* ar = (const float4*)(Ae + (size_t)c * D_DIM);
        const float4* xr = (const float4*)sx;
        float acc = 0.f;
        #pragma unroll 4
        for (int q = 0; q < D_DIM / 4; ++q) {        // ascending k, scalar chain
            float4 a = ar[q], b = xr[q];
            acc = fmaf(a.x, b.x, acc);
            acc = fmaf(a.y, b.y, acc);
            acc = fmaf(a.z, b.z, acc);
            acc = fmaf(a.w, b.w, acc);
        }
        float v = acc + g_beff[c];
        uint32_t bbits = __float_as_uint(v);
        uint32_t fk = (bbits & 0x80000000u) ? ~bbits : (bbits | 0x80000000u);
        skey[tid] = ((unsigned long long)fk << 32) | (uint32_t)(~(uint32_t)c);
    }
    __syncthreads();

    // bitonic sort (desc by val, ties: smaller idx first)
    for (int k = 2; k <= NSORT; k <<= 1) {
        for (int jj = k >> 1; jj > 0; jj >>= 1) {
            int p = tid ^ jj;
            if (p > tid) {
                bool up = ((tid & k) == 0);
                unsigned long long a = skey[tid], b = skey[p];
                bool sw = up ? (a < b) : (a > b);
                if (sw) { skey[tid] = b; skey[p] = a; }
            }
            __syncthreads();
        }
    }
    if (tid < K_TOP) {
        unsigned long long kk = skey[tid];
        uint32_t fk = (uint32_t)(kk >> 32);
        uint32_t b  = (fk & 0x80000000u) ? (fk ^ 0x80000000u) : ~fk;
        g_vals[row * K_TOP + tid] = fmaxf(__uint_as_float(b), 0.f);
        g_idx [row * K_TOP + tid] = (int)(~(uint32_t)kk);
    }
}

// ---------------- decode: out[n,:] = sum_j v_j * AdT[i_j,:] + bd -------------
__global__ __launch_bounds__(256) void decode_kernel(const float* __restrict__ bd,
                                                     float* __restrict__ out) {
    __shared__ float         sv[K_TOP];
    __shared__ const float4* sp[K_TOP];
    const int row = blockIdx.x;
    const int tid = threadIdx.x;
    if (tid < K_TOP) {
        sv[tid] = g_vals[row * K_TOP + tid];
        sp[tid] = (const float4*)(g_AdT + (size_t)g_idx[row * K_TOP + tid] * D_DIM);
    }
    __syncthreads();
    if (tid < D_DIM / 4) {
        float4 acc = ((const float4*)bd)[tid];
        #pragma unroll 8
        for (int j = 0; j < K_TOP; ++j) {
            float4 a = sp[j][tid];
            float  v = sv[j];
            acc.x = fmaf(v, a.x, acc.x);
            acc.y = fmaf(v, a.y, acc.y);
            acc.z = fmaf(v, a.z, acc.z);
            acc.w = fmaf(v, a.w, acc.w);
        }
        ((float4*)(out + (size_t)row * D_DIM))[tid] = acc;
    }
}

// ---------------- launch -----------------------------------------------------
extern "C" void kernel_launch(void* const* d_in, const int* in_sizes, int n_in,
                              void* d_out, int out_size) {
    const float* x  = (const float*)d_in[0];
    const float* Ae = (const float*)d_in[1];
    const float* be = (const float*)d_in[2];
    const float* Ad = (const float*)d_in[3];
    const float* bd = (const float*)d_in[4];
    float* out = (float*)d_out;

    __nv_bfloat16 *xb_p, *aeb_p;
    cudaGetSymbolAddress((void**)&xb_p,  g_xb);
    cudaGetSymbolAddress((void**)&aeb_p, g_aeb);

    const int gemm_smem = NSTAGE * STAGEB + 256;      // ~82 KB -> 2 CTAs/SM
    cudaFuncSetAttribute(gemm_kernel, cudaFuncAttributeMaxDynamicSharedMemorySize, gemm_smem);
    const int topk_smem = W_DIM * (int)sizeof(uint16_t);   // 48 KB
    cudaFuncSetAttribute(topk_kernel, cudaFuncAttributeMaxDynamicSharedMemorySize, topk_smem);

    cvt_kernel<<<(N_ROWS * D_DIM / 4 + 255) / 256, 256>>>(x,  xb_p,  N_ROWS * D_DIM / 4);
    cvt_kernel<<<(W_DIM * D_DIM / 4 + 255) / 256, 256>>>(Ae, aeb_p, W_DIM * D_DIM / 4);
    beff_kernel     <<<W_DIM / 8, 256>>>(be, bd, Ae);
    transpose_kernel<<<dim3(W_DIM / 32, D_DIM / 64), dim3(32, 8)>>>(Ad, 0);
    transpose_kernel<<<dim3(W_DIM / 32, D_DIM / 64), dim3(32, 8)>>>(Ad, D_DIM / 2);
    gemm_kernel     <<<dim3(W_DIM / 128, N_ROWS / 128), 256, gemm_smem>>>();
    topk_kernel     <<<N_ROWS, 256, topk_smem>>>();
    rescore_kernel  <<<N_ROWS, 256>>>(x, Ae);
    decode_kernel   <<<N_ROWS, 256>>>(bd, out);
}

// round 8
// speedup vs baseline: 1.1034x; 1.0292x over previous
#include <cuda_runtime.h>
#include <cuda_bf16.h>
#include <cstdint>

#define N_ROWS 8192
#define D_DIM  768
#define W_DIM  24576
#define K_TOP  64
#define NCAP   256     // candidate capacity
#define NSORT  256
#define THR_SLACK 8u   // bf16-key ulps of threshold slack

// ---------------- scratch (device globals) ---------------------------------
__device__ __align__(16) __nv_bfloat16 g_xb [(size_t)N_ROWS * D_DIM];
__device__ __align__(16) __nv_bfloat16 g_aeb[(size_t)W_DIM * D_DIM];
__device__ __align__(16) __nv_bfloat16 g_preb[(size_t)N_ROWS * W_DIM];   // 402 MB
__device__ __align__(16) float g_AdT[(size_t)W_DIM * D_DIM];             // 75 MB
__device__ float g_beff[W_DIM];
__device__ int   g_cand[(size_t)N_ROWS * NCAP];
__device__ int   g_candcnt[N_ROWS];
__device__ float g_vals[N_ROWS * K_TOP];
__device__ int   g_idx [N_ROWS * K_TOP];

// ---------------- helpers ----------------------------------------------------
__device__ __forceinline__ uint32_t smem_u32(const void* p) {
    uint32_t a;
    asm("{ .reg .u64 t; cvta.to.shared.u64 t, %1; cvt.u32.u64 %0, t; }"
        : "=r"(a) : "l"(p));
    return a;
}
#define CP16(sa, g) asm volatile("cp.async.cg.shared.global [%0], [%1], 16;" :: "r"(sa), "l"(g))
#define CP_COMMIT() asm volatile("cp.async.commit_group;" ::: "memory")
#define CP_WAIT3()  asm volatile("cp.async.wait_group 3;" ::: "memory")

#define LDSM4(r0, r1, r2, r3, a) \
    asm volatile("ldmatrix.sync.aligned.m8n8.x4.shared.b16 {%0,%1,%2,%3}, [%4];" \
                 : "=r"(r0), "=r"(r1), "=r"(r2), "=r"(r3) : "r"(a))

__device__ __forceinline__ void mma16816(float* c, const uint32_t* a, const uint32_t* b) {
    asm volatile("mma.sync.aligned.m16n8k16.row.col.f32.bf16.bf16.f32 "
                 "{%0,%1,%2,%3}, {%4,%5,%6,%7}, {%8,%9}, {%0,%1,%2,%3};"
                 : "+f"(c[0]), "+f"(c[1]), "+f"(c[2]), "+f"(c[3])
                 : "r"(a[0]), "r"(a[1]), "r"(a[2]), "r"(a[3]), "r"(b[0]), "r"(b[1]));
}

// ---------------- fp32 -> bf16 convert --------------------------------------
__global__ __launch_bounds__(256) void cvt_kernel(const float* __restrict__ src,
                                                  __nv_bfloat16* __restrict__ dst, int n4) {
    int i = blockIdx.x * 256 + threadIdx.x;
    if (i >= n4) return;
    float4 v = ((const float4*)src)[i];
    uint32_t p0, p1;
    asm("cvt.rn.bf16x2.f32 %0, %1, %2;" : "=r"(p0) : "f"(v.y), "f"(v.x));
    asm("cvt.rn.bf16x2.f32 %0, %1, %2;" : "=r"(p1) : "f"(v.w), "f"(v.z));
    ((uint2*)dst)[i] = make_uint2(p0, p1);
}

// ---------------- beff[w] = be[w] - dot(bd, Ae[w,:]) ------------------------
__global__ __launch_bounds__(256) void beff_kernel(const float* __restrict__ be,
                                                   const float* __restrict__ bd,
                                                   const float* __restrict__ Ae) {
    int w    = blockIdx.x * 8 + (threadIdx.x >> 5);
    int lane = threadIdx.x & 31;
    const float* row = Ae + (size_t)w * D_DIM;
    float s = 0.f;
    for (int d = lane; d < D_DIM; d += 32) s += bd[d] * row[d];
    #pragma unroll
    for (int o = 16; o > 0; o >>= 1) s += __shfl_down_sync(0xffffffffu, s, o);
    if (lane == 0) g_beff[w] = be[w] - s;
}

// ---------------- AdT[w,d] = Ad[d,w] ----------------------------------------
__global__ __launch_bounds__(256) void transpose_kernel(const float* __restrict__ Ad) {
    __shared__ float tile[32][33];
    int w0 = blockIdx.x * 32;
    int d0 = blockIdx.y * 32;
    int tx = threadIdx.x, ty = threadIdx.y;   // 32 x 8
    #pragma unroll
    for (int i = 0; i < 32; i += 8)
        tile[ty + i][tx] = Ad[(size_t)(d0 + ty + i) * W_DIM + w0 + tx];
    __syncthreads();
    #pragma unroll
    for (int i = 0; i < 32; i += 8)
        g_AdT[(size_t)(w0 + ty + i) * D_DIM + d0 + tx] = tile[tx][ty + i];
}

// ---------------- bf16 HMMA GEMM: preb = Xb @ Aeb^T + beff -------------------
// CTA tile 128x128, BK=32, 5-stage cp.async pipeline, 8 warps (2x4),
// warp tile 64x32, 2 CTAs/SM.
#define GBK     32
#define NSTAGE  5
#define ROWPITCH 80                       // 64B data + 16B pad
#define ASTAGE  (128 * ROWPITCH)
#define STAGEB  (2 * ASTAGE)              // 20480
#define KT      (D_DIM / GBK)             // 24

__global__ __launch_bounds__(256, 2) void gemm_kernel() {
    extern __shared__ char smem[];
    const uint32_t SB = (smem_u32(smem) + 127u) & ~127u;
    const int tid  = threadIdx.x;
    const int wid  = tid >> 5;
    const int lane = tid & 31;
    const int wm   = wid & 1;
    const int wn   = wid >> 1;

    const __nv_bfloat16* Ag = g_xb  + (size_t)(blockIdx.y * 128) * D_DIM;
    const __nv_bfloat16* Bg = g_aeb + (size_t)(blockIdx.x * 128) * D_DIM;

    const int lrow = tid >> 2;
    const int lcol = tid & 3;

    auto load_stage = [&](int s, int k0) {
        const uint32_t ab = SB + s * STAGEB;
        const uint32_t bb = ab + ASTAGE;
        #pragma unroll
        for (int h = 0; h < 2; ++h) {
            int r = lrow + h * 64;
            CP16(ab + r * ROWPITCH + lcol * 16, Ag + (size_t)r * D_DIM + k0 + lcol * 8);
            CP16(bb + r * ROWPITCH + lcol * 16, Bg + (size_t)r * D_DIM + k0 + lcol * 8);
        }
    };

    float acc[4][4][4];
    #pragma unroll
    for (int i = 0; i < 4; ++i)
        #pragma unroll
        for (int j = 0; j < 4; ++j)
            #pragma unroll
            for (int q = 0; q < 4; ++q) acc[i][j][q] = 0.f;

    load_stage(0, 0);  CP_COMMIT();
    load_stage(1, 32); CP_COMMIT();
    load_stage(2, 64); CP_COMMIT();
    load_stage(3, 96); CP_COMMIT();

    const int a_row = (lane & 15);
    const int a_kb  = (lane >> 4) * 16;
    const int b_row = ((lane >> 4) & 1) * 8 + (lane & 7);
    const int b_kb  = ((lane >> 3) & 1) * 16;

    for (int it = 0; it < KT; ++it) {
        CP_WAIT3();
        __syncthreads();
        {
            int nx = it + 4;
            if (nx < KT) load_stage(nx % NSTAGE, nx * GBK);
            CP_COMMIT();
        }

        const uint32_t ab = SB + (it % NSTAGE) * STAGEB;
        const uint32_t bb = ab + ASTAGE;
        #pragma unroll
        for (int ks = 0; ks < 2; ++ks) {
            uint32_t af[4][4], bf[2][4];
            #pragma unroll
            for (int mt = 0; mt < 4; ++mt) {
                uint32_t addr = ab + (wm * 64 + mt * 16 + a_row) * ROWPITCH
                              + a_kb + ks * 32;
                LDSM4(af[mt][0], af[mt][1], af[mt][2], af[mt][3], addr);
            }
            #pragma unroll
            for (int bt = 0; bt < 2; ++bt) {
                uint32_t addr = bb + (wn * 32 + bt * 16 + b_row) * ROWPITCH
                              + b_kb + ks * 32;
                LDSM4(bf[bt][0], bf[bt][1], bf[bt][2], bf[bt][3], addr);
            }
            #pragma unroll
            for (int mt = 0; mt < 4; ++mt)
                #pragma unroll
                for (int nt = 0; nt < 4; ++nt)
                    mma16816(acc[mt][nt], af[mt], &bf[nt >> 1][(nt & 1) * 2]);
        }
        __syncthreads();
    }

    const int g  = lane >> 2;
    const int tg = lane & 3;
    const int rowBase = blockIdx.y * 128 + wm * 64;
    const int colBase = blockIdx.x * 128 + wn * 32;
    #pragma unroll
    for (int nt = 0; nt < 4; ++nt) {
        const int c = colBase + nt * 8 + tg * 2;
        const float bz0 = g_beff[c], bz1 = g_beff[c + 1];
        #pragma unroll
        for (int mt = 0; mt < 4; ++mt) {
            const int r0 = rowBase + mt * 16 + g;
            uint32_t p0, p1;
            float v00 = acc[mt][nt][0] + bz0, v01 = acc[mt][nt][1] + bz1;
            float v10 = acc[mt][nt][2] + bz0, v11 = acc[mt][nt][3] + bz1;
            asm("cvt.rn.bf16x2.f32 %0, %1, %2;" : "=r"(p0) : "f"(v01), "f"(v00));
            asm("cvt.rn.bf16x2.f32 %0, %1, %2;" : "=r"(p1) : "f"(v11), "f"(v10));
            *(uint32_t*)(g_preb + (size_t)r0 * W_DIM + c)       = p0;
            *(uint32_t*)(g_preb + (size_t)(r0 + 8) * W_DIM + c) = p1;
        }
    }
}

// ---------------- per-row candidate select (bf16 keys, slack threshold) -----
__global__ __launch_bounds__(256) void topk_kernel() {
    extern __shared__ uint16_t sk[];          // W_DIM keys (48KB)
    __shared__ uint32_t hist[256];
    __shared__ uint32_t s_b1, s_need, s_thr, s_cnt;

    const int tid = threadIdx.x;
    const int row = blockIdx.x;
    const uint4* src = (const uint4*)(g_preb + (size_t)row * W_DIM);

    hist[tid] = 0u;
    if (tid == 0) s_cnt = 0u;
    __syncthreads();

    // fused: convert to order-preserving u16 keys + level-1 histogram (high byte)
    for (int i = tid; i < W_DIM / 8; i += 256) {
        uint4 v = src[i];
        uint32_t w[4] = {v.x, v.y, v.z, v.w};
        #pragma unroll
        for (int q = 0; q < 4; ++q) {
            uint16_t lo = (uint16_t)(w[q] & 0xFFFF), hi = (uint16_t)(w[q] >> 16);
            uint16_t k0 = (lo & 0x8000) ? (uint16_t)~lo : (uint16_t)(lo | 0x8000);
            uint16_t k1 = (hi & 0x8000) ? (uint16_t)~hi : (uint16_t)(hi | 0x8000);
            sk[i * 8 + q * 2 + 0] = k0;
            sk[i * 8 + q * 2 + 1] = k1;
            int bin0 = k0 >> 8;
            unsigned m0 = __match_any_sync(0xffffffffu, bin0);
            if ((tid & 31) == (__ffs(m0) - 1)) atomicAdd(&hist[bin0], (uint32_t)__popc(m0));
            int bin1 = k1 >> 8;
            unsigned m1 = __match_any_sync(0xffffffffu, bin1);
            if ((tid & 31) == (__ffs(m1) - 1)) atomicAdd(&hist[bin1], (uint32_t)__popc(m1));
        }
    }
    __syncthreads();
    if (tid == 0) {
        uint32_t cum = 0u; int b1 = 0;
        for (int b = 255; b >= 0; --b) {
            if (cum + hist[b] >= 128u) { b1 = b; break; }
            cum += hist[b];
        }
        s_b1 = (uint32_t)b1; s_need = 128u - cum;
    }
    __syncthreads();
    const uint32_t b1 = s_b1;
    hist[tid] = 0u;
    __syncthreads();

    // level 2: low byte within bin b1
    for (int i = tid; i < W_DIM; i += 256) {
        uint16_t u = sk[i];
        int bin = ((u >> 8) == b1) ? (int)(u & 0xFF) : -1;
        unsigned m = __match_any_sync(0xffffffffu, bin);
        if (bin >= 0 && (tid & 31) == (__ffs(m) - 1))
            atomicAdd(&hist[bin], (uint32_t)__popc(m));
    }
    __syncthreads();
    if (tid == 0) {
        uint32_t need = s_need, cum = 0u; int b2 = 0;
        for (int b = 255; b >= 0; --b) {
            if (cum + hist[b] >= need) { b2 = b; break; }
            cum += hist[b];
        }
        uint32_t thr = (b1 << 8) | (uint32_t)b2;
        s_thr = (thr > THR_SLACK) ? thr - THR_SLACK : 0u;
    }
    __syncthreads();
    const uint32_t thr = s_thr;
    int* crow = g_cand + (size_t)row * NCAP;

    for (int i = tid; i < W_DIM; i += 256) {
        if ((uint32_t)sk[i] >= thr) {
            int pos = (int)atomicAdd(&s_cnt, 1u);
            if (pos < NCAP) crow[pos] = i;
        }
    }
    __syncthreads();
    if (tid == 0) g_candcnt[row] = (s_cnt < NCAP) ? (int)s_cnt : NCAP;
}

// ---------------- exact fp32 rescore: ONE THREAD PER CANDIDATE --------------
// FROZEN accumulation order: ascending-k scalar fmaf chain (matches reference).
__global__ __launch_bounds__(256) void rescore_kernel(const float* __restrict__ x,
                                                      const float* __restrict__ Ae) {
    __shared__ __align__(16) float sx[D_DIM];
    __shared__ unsigned long long skey[NSORT];

    const int tid = threadIdx.x, row = blockIdx.x;
    const int cnt = g_candcnt[row];
    for (int i = tid; i < D_DIM / 4; i += 256)
        ((float4*)sx)[i] = ((const float4*)(x + (size_t)row * D_DIM))[i];
    skey[tid] = 0ull;
    __syncthreads();

    if (tid < cnt) {
        const int c = g_cand[(size_t)row * NCAP + tid];
        const float4* ar = (const float4*)(Ae + (size_t)c * D_DIM);
        const float4* xr = (const float4*)sx;
        float acc = 0.f;
        #pragma unroll 4
        for (int q = 0; q < D_DIM / 4; ++q) {        // ascending k, scalar chain
            float4 a = ar[q], b = xr[q];
            acc = fmaf(a.x, b.x, acc);
            acc = fmaf(a.y, b.y, acc);
            acc = fmaf(a.z, b.z, acc);
            acc = fmaf(a.w, b.w, acc);
        }
        float v = acc + g_beff[c];
        uint32_t bbits = __float_as_uint(v);
        uint32_t fk = (bbits & 0x80000000u) ? ~bbits : (bbits | 0x80000000u);
        skey[tid] = ((unsigned long long)fk << 32) | (uint32_t)(~(uint32_t)c);
    }
    __syncthreads();

    // bitonic sort (desc by val, ties: smaller idx first)
    for (int k = 2; k <= NSORT; k <<= 1) {
        for (int jj = k >> 1; jj > 0; jj >>= 1) {
            int p = tid ^ jj;
            if (p > tid) {
                bool up = ((tid & k) == 0);
                unsigned long long a = skey[tid], b = skey[p];
                bool sw = up ? (a < b) : (a > b);
                if (sw) { skey[tid] = b; skey[p] = a; }
            }
            __syncthreads();
        }
    }
    if (tid < K_TOP) {
        unsigned long long kk = skey[tid];
        uint32_t fk = (uint32_t)(kk >> 32);
        uint32_t b  = (fk & 0x80000000u) ? (fk ^ 0x80000000u) : ~fk;
        g_vals[row * K_TOP + tid] = fmaxf(__uint_as_float(b), 0.f);
        g_idx [row * K_TOP + tid] = (int)(~(uint32_t)kk);
    }
}

// ---------------- decode: out[n,:] = sum_j v_j * AdT[i_j,:] + bd -------------
__global__ __launch_bounds__(256) void decode_kernel(const float* __restrict__ bd,
                                                     float* __restrict__ out) {
    __shared__ float         sv[K_TOP];
    __shared__ const float4* sp[K_TOP];
    const int row = blockIdx.x;
    const int tid = threadIdx.x;
    if (tid < K_TOP) {
        sv[tid] = g_vals[row * K_TOP + tid];
        sp[tid] = (const float4*)(g_AdT + (size_t)g_idx[row * K_TOP + tid] * D_DIM);
    }
    __syncthreads();
    if (tid < D_DIM / 4) {
        float4 acc = ((const float4*)bd)[tid];
        #pragma unroll 8
        for (int j = 0; j < K_TOP; ++j) {
            float4 a = sp[j][tid];
            float  v = sv[j];
            acc.x = fmaf(v, a.x, acc.x);
            acc.y = fmaf(v, a.y, acc.y);
            acc.z = fmaf(v, a.z, acc.z);
            acc.w = fmaf(v, a.w, acc.w);
        }
        ((float4*)(out + (size_t)row * D_DIM))[tid] = acc;
    }
}

// ---------------- launch -----------------------------------------------------
extern "C" void kernel_launch(void* const* d_in, const int* in_sizes, int n_in,
                              void* d_out, int out_size) {
    const float* x  = (const float*)d_in[0];
    const float* Ae = (const float*)d_in[1];
    const float* be = (const float*)d_in[2];
    const float* Ad = (const float*)d_in[3];
    const float* bd = (const float*)d_in[4];
    float* out = (float*)d_out;

    __nv_bfloat16 *xb_p, *aeb_p;
    cudaGetSymbolAddress((void**)&xb_p,  g_xb);
    cudaGetSymbolAddress((void**)&aeb_p, g_aeb);

    const int gemm_smem = NSTAGE * STAGEB + 256;      // ~102.6 KB -> 2 CTAs/SM
    cudaFuncSetAttribute(gemm_kernel, cudaFuncAttributeMaxDynamicSharedMemorySize, gemm_smem);
    const int topk_smem = W_DIM * (int)sizeof(uint16_t);   // 48 KB
    cudaFuncSetAttribute(topk_kernel, cudaFuncAttributeMaxDynamicSharedMemorySize, topk_smem);

    // order chosen so gemm_kernel sits at ncu's capture slot (5th launch)
    transpose_kernel<<<dim3(W_DIM / 32, D_DIM / 32), dim3(32, 8)>>>(Ad);
    cvt_kernel<<<(N_ROWS * D_DIM / 4 + 255) / 256, 256>>>(x,  xb_p,  N_ROWS * D_DIM / 4);
    cvt_kernel<<<(W_DIM * D_DIM / 4 + 255) / 256, 256>>>(Ae, aeb_p, W_DIM * D_DIM / 4);
    beff_kernel     <<<W_DIM / 8, 256>>>(be, bd, Ae);
    gemm_kernel     <<<dim3(W_DIM / 128, N_ROWS / 128), 256, gemm_smem>>>();
    topk_kernel     <<<N_ROWS, 256, topk_smem>>>();
    rescore_kernel  <<<N_ROWS, 256>>>(x, Ae);
    decode_kernel   <<<N_ROWS, 256>>>(bd, out);
}

// round 11
// speedup vs baseline: 1.1713x; 1.0616x over previous
#include <cuda_runtime.h>
#include <cuda_bf16.h>
#include <cstdint>

#define N_ROWS 8192
#define D_DIM  768
#define W_DIM  24576
#define K_TOP  64
#define NCAP   256     // candidate capacity
#define NSORT  256
#define THR_SLACK 4u   // bf16-key ulps of threshold slack (~0.031 in value)

// ---------------- scratch (device globals) ---------------------------------
__device__ __align__(16) __nv_bfloat16 g_xb [(size_t)N_ROWS * D_DIM];
__device__ __align__(16) __nv_bfloat16 g_aeb[(size_t)W_DIM * D_DIM];
__device__ __align__(16) __nv_bfloat16 g_preb[(size_t)N_ROWS * W_DIM];   // 402 MB
__device__ __align__(16) float g_AdT[(size_t)W_DIM * D_DIM];             // 75 MB
__device__ float g_beff[W_DIM];
__device__ int   g_cand[(size_t)N_ROWS * NCAP];
__device__ int   g_candcnt[N_ROWS];
__device__ float g_vals[N_ROWS * K_TOP];
__device__ int   g_idx [N_ROWS * K_TOP];

// ---------------- helpers ----------------------------------------------------
__device__ __forceinline__ uint32_t smem_u32(const void* p) {
    uint32_t a;
    asm("{ .reg .u64 t; cvta.to.shared.u64 t, %1; cvt.u32.u64 %0, t; }"
        : "=r"(a) : "l"(p));
    return a;
}
#define CP16(sa, g) asm volatile("cp.async.cg.shared.global [%0], [%1], 16;" :: "r"(sa), "l"(g))
#define CP_COMMIT() asm volatile("cp.async.commit_group;" ::: "memory")
#define CP_WAIT3()  asm volatile("cp.async.wait_group 3;" ::: "memory")

#define LDSM4(r0, r1, r2, r3, a) \
    asm volatile("ldmatrix.sync.aligned.m8n8.x4.shared.b16 {%0,%1,%2,%3}, [%4];" \
                 : "=r"(r0), "=r"(r1), "=r"(r2), "=r"(r3) : "r"(a))

__device__ __forceinline__ void mma16816(float* c, const uint32_t* a, const uint32_t* b) {
    asm volatile("mma.sync.aligned.m16n8k16.row.col.f32.bf16.bf16.f32 "
                 "{%0,%1,%2,%3}, {%4,%5,%6,%7}, {%8,%9}, {%0,%1,%2,%3};"
                 : "+f"(c[0]), "+f"(c[1]), "+f"(c[2]), "+f"(c[3])
                 : "r"(a[0]), "r"(a[1]), "r"(a[2]), "r"(a[3]), "r"(b[0]), "r"(b[1]));
}

// ---------------- fp32 -> bf16 convert --------------------------------------
__global__ __launch_bounds__(256) void cvt_kernel(const float* __restrict__ src,
                                                  __nv_bfloat16* __restrict__ dst, int n4) {
    int i = blockIdx.x * 256 + threadIdx.x;
    if (i >= n4) return;
    float4 v = ((const float4*)src)[i];
    uint32_t p0, p1;
    asm("cvt.rn.bf16x2.f32 %0, %1, %2;" : "=r"(p0) : "f"(v.y), "f"(v.x));
    asm("cvt.rn.bf16x2.f32 %0, %1, %2;" : "=r"(p1) : "f"(v.w), "f"(v.z));
    ((uint2*)dst)[i] = make_uint2(p0, p1);
}

// ---------------- beff[w] = be[w] - dot(bd, Ae[w,:]) ------------------------
__global__ __launch_bounds__(256) void beff_kernel(const float* __restrict__ be,
                                                   const float* __restrict__ bd,
                                                   const float* __restrict__ Ae) {
    int w    = blockIdx.x * 8 + (threadIdx.x >> 5);
    int lane = threadIdx.x & 31;
    const float* row = Ae + (size_t)w * D_DIM;
    float s = 0.f;
    for (int d = lane; d < D_DIM; d += 32) s += bd[d] * row[d];
    #pragma unroll
    for (int o = 16; o > 0; o >>= 1) s += __shfl_down_sync(0xffffffffu, s, o);
    if (lane == 0) g_beff[w] = be[w] - s;
}

// ---------------- AdT[w,d] = Ad[d,w] ----------------------------------------
__global__ __launch_bounds__(256) void transpose_kernel(const float* __restrict__ Ad) {
    __shared__ float tile[32][33];
    int w0 = blockIdx.x * 32;
    int d0 = blockIdx.y * 32;
    int tx = threadIdx.x, ty = threadIdx.y;   // 32 x 8
    #pragma unroll
    for (int i = 0; i < 32; i += 8)
        tile[ty + i][tx] = Ad[(size_t)(d0 + ty + i) * W_DIM + w0 + tx];
    __syncthreads();
    #pragma unroll
    for (int i = 0; i < 32; i += 8)
        g_AdT[(size_t)(w0 + ty + i) * D_DIM + d0 + tx] = tile[tx][ty + i];
}

// ---------------- bf16 HMMA GEMM: preb = Xb @ Aeb^T + beff -------------------
// CTA tile 128x128, BK=32, 5-stage cp.async pipeline, 8 warps (2x4),
// warp tile 64x32, 2 CTAs/SM. ONE barrier per mainloop iteration.
#define GBK     32
#define NSTAGE  5
#define ROWPITCH 80                       // 64B data + 16B pad
#define ASTAGE  (128 * ROWPITCH)
#define STAGEB  (2 * ASTAGE)              // 20480
#define KT      (D_DIM / GBK)             // 24

__global__ __launch_bounds__(256, 2) void gemm_kernel() {
    extern __shared__ char smem[];
    const uint32_t SB = (smem_u32(smem) + 127u) & ~127u;
    const int tid  = threadIdx.x;
    const int wid  = tid >> 5;
    const int lane = tid & 31;
    const int wm   = wid & 1;
    const int wn   = wid >> 1;

    const __nv_bfloat16* Ag = g_xb  + (size_t)(blockIdx.y * 128) * D_DIM;
    const __nv_bfloat16* Bg = g_aeb + (size_t)(blockIdx.x * 128) * D_DIM;

    const int lrow = tid >> 2;
    const int lcol = tid & 3;

    auto load_stage = [&](int s, int k0) {
        const uint32_t ab = SB + s * STAGEB;
        const uint32_t bb = ab + ASTAGE;
        #pragma unroll
        for (int h = 0; h < 2; ++h) {
            int r = lrow + h * 64;
            CP16(ab + r * ROWPITCH + lcol * 16, Ag + (size_t)r * D_DIM + k0 + lcol * 8);
            CP16(bb + r * ROWPITCH + lcol * 16, Bg + (size_t)r * D_DIM + k0 + lcol * 8);
        }
    };

    float acc[4][4][4];
    #pragma unroll
    for (int i = 0; i < 4; ++i)
        #pragma unroll
        for (int j = 0; j < 4; ++j)
            #pragma unroll
            for (int q = 0; q < 4; ++q) acc[i][j][q] = 0.f;

    load_stage(0, 0);  CP_COMMIT();
    load_stage(1, 32); CP_COMMIT();
    load_stage(2, 64); CP_COMMIT();
    load_stage(3, 96); CP_COMMIT();

    const int a_row = (lane & 15);
    const int a_kb  = (lane >> 4) * 16;
    const int b_row = ((lane >> 4) & 1) * 8 + (lane & 7);
    const int b_kb  = ((lane >> 3) & 1) * 16;

    for (int it = 0; it < KT; ++it) {
        CP_WAIT3();
        __syncthreads();   // single barrier: also proves all ldsm of it-1 done
        {
            int nx = it + 4;
            if (nx < KT) load_stage(nx % NSTAGE, nx * GBK);
            CP_COMMIT();
        }

        const uint32_t ab = SB + (it % NSTAGE) * STAGEB;
        const uint32_t bb = ab + ASTAGE;
        #pragma unroll
        for (int ks = 0; ks < 2; ++ks) {
            uint32_t af[4][4], bf[2][4];
            #pragma unroll
            for (int mt = 0; mt < 4; ++mt) {
                uint32_t addr = ab + (wm * 64 + mt * 16 + a_row) * ROWPITCH
                              + a_kb + ks * 32;
                LDSM4(af[mt][0], af[mt][1], af[mt][2], af[mt][3], addr);
            }
            #pragma unroll
            for (int bt = 0; bt < 2; ++bt) {
                uint32_t addr = bb + (wn * 32 + bt * 16 + b_row) * ROWPITCH
                              + b_kb + ks * 32;
                LDSM4(bf[bt][0], bf[bt][1], bf[bt][2], bf[bt][3], addr);
            }
            #pragma unroll
            for (int mt = 0; mt < 4; ++mt)
                #pragma unroll
                for (int nt = 0; nt < 4; ++nt)
                    mma16816(acc[mt][nt], af[mt], &bf[nt >> 1][(nt & 1) * 2]);
        }
    }

    const int g  = lane >> 2;
    const int tg = lane & 3;
    const int rowBase = blockIdx.y * 128 + wm * 64;
    const int colBase = blockIdx.x * 128 + wn * 32;
    #pragma unroll
    for (int nt = 0; nt < 4; ++nt) {
        const int c = colBase + nt * 8 + tg * 2;
        const float bz0 = g_beff[c], bz1 = g_beff[c + 1];
        #pragma unroll
        for (int mt = 0; mt < 4; ++mt) {
            const int r0 = rowBase + mt * 16 + g;
            uint32_t p0, p1;
            float v00 = acc[mt][nt][0] + bz0, v01 = acc[mt][nt][1] + bz1;
            float v10 = acc[mt][nt][2] + bz0, v11 = acc[mt][nt][3] + bz1;
            asm("cvt.rn.bf16x2.f32 %0, %1, %2;" : "=r"(p0) : "f"(v01), "f"(v00));
            asm("cvt.rn.bf16x2.f32 %0, %1, %2;" : "=r"(p1) : "f"(v11), "f"(v10));
            *(uint32_t*)(g_preb + (size_t)r0 * W_DIM + c)       = p0;
            *(uint32_t*)(g_preb + (size_t)(r0 + 8) * W_DIM + c) = p1;
        }
    }
}

// ---------------- per-row candidate select (bf16 keys, slack threshold) -----
__global__ __launch_bounds__(256) void topk_kernel() {
    extern __shared__ uint16_t sk[];          // W_DIM keys (48KB)
    __shared__ uint32_t hist[256];
    __shared__ uint32_t s_b1, s_need, s_thr, s_cnt;

    const int tid = threadIdx.x;
    const int row = blockIdx.x;
    const uint4* src = (const uint4*)(g_preb + (size_t)row * W_DIM);

    hist[tid] = 0u;
    if (tid == 0) s_cnt = 0u;
    __syncthreads();

    // fused: convert to order-preserving u16 keys + level-1 histogram (high byte)
    for (int i = tid; i < W_DIM / 8; i += 256) {
        uint4 v = src[i];
        uint32_t w[4] = {v.x, v.y, v.z, v.w};
        #pragma unroll
        for (int q = 0; q < 4; ++q) {
            uint16_t lo = (uint16_t)(w[q] & 0xFFFF), hi = (uint16_t)(w[q] >> 16);
            uint16_t k0 = (lo & 0x8000) ? (uint16_t)~lo : (uint16_t)(lo | 0x8000);
            uint16_t k1 = (hi & 0x8000) ? (uint16_t)~hi : (uint16_t)(hi | 0x8000);
            sk[i * 8 + q * 2 + 0] = k0;
            sk[i * 8 + q * 2 + 1] = k1;
            int bin0 = k0 >> 8;
            unsigned m0 = __match_any_sync(0xffffffffu, bin0);
            if ((tid & 31) == (__ffs(m0) - 1)) atomicAdd(&hist[bin0], (uint32_t)__popc(m0));
            int bin1 = k1 >> 8;
            unsigned m1 = __match_any_sync(0xffffffffu, bin1);
            if ((tid & 31) == (__ffs(m1) - 1)) atomicAdd(&hist[bin1], (uint32_t)__popc(m1));
        }
    }
    __syncthreads();
    if (tid == 0) {
        uint32_t cum = 0u; int b1 = 0;
        for (int b = 255; b >= 0; --b) {
            if (cum + hist[b] >= 128u) { b1 = b; break; }
            cum += hist[b];
        }
        s_b1 = (uint32_t)b1; s_need = 128u - cum;
    }
    __syncthreads();
    const uint32_t b1 = s_b1;
    hist[tid] = 0u;
    __syncthreads();

    // level 2: low byte within bin b1
    for (int i = tid; i < W_DIM; i += 256) {
        uint16_t u = sk[i];
        int bin = ((u >> 8) == b1) ? (int)(u & 0xFF) : -1;
        unsigned m = __match_any_sync(0xffffffffu, bin);
        if (bin >= 0 && (tid & 31) == (__ffs(m) - 1))
            atomicAdd(&hist[bin], (uint32_t)__popc(m));
    }
    __syncthreads();
    if (tid == 0) {
        uint32_t need = s_need, cum = 0u; int b2 = 0;
        for (int b = 255; b >= 0; --b) {
            if (cum + hist[b] >= need) { b2 = b; break; }
            cum += hist[b];
        }
        uint32_t thr = (b1 << 8) | (uint32_t)b2;
        s_thr = (thr > THR_SLACK) ? thr - THR_SLACK : 0u;
    }
    __syncthreads();
    const uint32_t thr = s_thr;
    int* crow = g_cand + (size_t)row * NCAP;

    for (int i = tid; i < W_DIM; i += 256) {
        if ((uint32_t)sk[i] >= thr) {
            int pos = (int)atomicAdd(&s_cnt, 1u);
            if (pos < NCAP) crow[pos] = i;
        }
    }
    __syncthreads();
    if (tid == 0) g_candcnt[row] = (s_cnt < NCAP) ? (int)s_cnt : NCAP;
}

// ---------------- exact fp32 rescore: ONE THREAD PER CANDIDATE --------------
// FROZEN accumulation order: ascending-k scalar fmaf chain (matches reference).
__global__ __launch_bounds__(256) void rescore_kernel(const float* __restrict__ x,
                                                      const float* __restrict__ Ae) {
    __shared__ __align__(16) float sx[D_DIM];
    __shared__ unsigned long long skey[NSORT];

    const int tid = threadIdx.x, row = blockIdx.x;
    const int cnt = g_candcnt[row];
    for (int i = tid; i < D_DIM / 4; i += 256)
        ((float4*)sx)[i] = ((const float4*)(x + (size_t)row * D_DIM))[i];
    skey[tid] = 0ull;
    __syncthreads();

    if (tid < cnt) {
        const int c = g_cand[(size_t)row * NCAP + tid];
        const float4* ar = (const float4*)(Ae + (size_t)c * D_DIM);
        const float4* xr = (const float4*)sx;
        float acc = 0.f;
        #pragma unroll 4
        for (int q = 0; q < D_DIM / 4; ++q) {        // ascending k, scalar chain
            float4 a = ar[q], b = xr[q];
            acc = fmaf(a.x, b.x, acc);
            acc = fmaf(a.y, b.y, acc);
            acc = fmaf(a.z, b.z, acc);
            acc = fmaf(a.w, b.w, acc);
        }
        float v = acc + g_beff[c];
        uint32_t bbits = __float_as_uint(v);
        uint32_t fk = (bbits & 0x80000000u) ? ~bbits : (bbits | 0x80000000u);
        skey[tid] = ((unsigned long long)fk << 32) | (uint32_t)(~(uint32_t)c);
    }
    __syncthreads();

    // bitonic sort (desc by val, ties: smaller idx first)
    for (int k = 2; k <= NSORT; k <<= 1) {
        for (int jj = k >> 1; jj > 0; jj >>= 1) {
            int p = tid ^ jj;
            if (p > tid) {
                bool up = ((tid & k) == 0);
                unsigned long long a = skey[tid], b = skey[p];
                bool sw = up ? (a < b) : (a > b);
                if (sw) { skey[tid] = b; skey[p] = a; }
            }
            __syncthreads();
        }
    }
    if (tid < K_TOP) {
        unsigned long long kk = skey[tid];
        uint32_t fk = (uint32_t)(kk >> 32);
        uint32_t b  = (fk & 0x80000000u) ? (fk ^ 0x80000000u) : ~fk;
        g_vals[row * K_TOP + tid] = fmaxf(__uint_as_float(b), 0.f);
        g_idx [row * K_TOP + tid] = (int)(~(uint32_t)kk);
    }
}

// ---------------- decode: out[n,:] = sum_j v_j * AdT[i_j,:] + bd -------------
__global__ __launch_bounds__(256) void decode_kernel(const float* __restrict__ bd,
                                                     float* __restrict__ out) {
    __shared__ float         sv[K_TOP];
    __shared__ const float4* sp[K_TOP];
    const int row = blockIdx.x;
    const int tid = threadIdx.x;
    if (tid < K_TOP) {
        sv[tid] = g_vals[row * K_TOP + tid];
        sp[tid] = (const float4*)(g_AdT + (size_t)g_idx[row * K_TOP + tid] * D_DIM);
    }
    __syncthreads();
    if (tid < D_DIM / 4) {
        float4 acc = ((const float4*)bd)[tid];
        #pragma unroll 8
        for (int j = 0; j < K_TOP; ++j) {
            float4 a = sp[j][tid];
            float  v = sv[j];
            acc.x = fmaf(v, a.x, acc.x);
            acc.y = fmaf(v, a.y, acc.y);
            acc.z = fmaf(v, a.z, acc.z);
            acc.w = fmaf(v, a.w, acc.w);
        }
        ((float4*)(out + (size_t)row * D_DIM))[tid] = acc;
    }
}

// ---------------- launch -----------------------------------------------------
extern "C" void kernel_launch(void* const* d_in, const int* in_sizes, int n_in,
                              void* d_out, int out_size) {
    const float* x  = (const float*)d_in[0];
    const float* Ae = (const float*)d_in[1];
    const float* be = (const float*)d_in[2];
    const float* Ad = (const float*)d_in[3];
    const float* bd = (const float*)d_in[4];
    float* out = (float*)d_out;

    __nv_bfloat16 *xb_p, *aeb_p;
    cudaGetSymbolAddress((void**)&xb_p,  g_xb);
    cudaGetSymbolAddress((void**)&aeb_p, g_aeb);

    const int gemm_smem = NSTAGE * STAGEB + 256;      // ~102.6 KB -> 2 CTAs/SM
    cudaFuncSetAttribute(gemm_kernel, cudaFuncAttributeMaxDynamicSharedMemorySize, gemm_smem);
    const int topk_smem = W_DIM * (int)sizeof(uint16_t);   // 48 KB
    cudaFuncSetAttribute(topk_kernel, cudaFuncAttributeMaxDynamicSharedMemorySize, topk_smem);

    // gemm is the 4th launch -> lands at ncu's capture slot
    cvt_kernel<<<(N_ROWS * D_DIM / 4 + 255) / 256, 256>>>(x,  xb_p,  N_ROWS * D_DIM / 4);
    cvt_kernel<<<(W_DIM * D_DIM / 4 + 255) / 256, 256>>>(Ae, aeb_p, W_DIM * D_DIM / 4);
    beff_kernel     <<<W_DIM / 8, 256>>>(be, bd, Ae);
    gemm_kernel     <<<dim3(W_DIM / 128, N_ROWS / 128), 256, gemm_smem>>>();
    transpose_kernel<<<dim3(W_DIM / 32, D_DIM / 32), dim3(32, 8)>>>(Ad);
    topk_kernel     <<<N_ROWS, 256, topk_smem>>>();
    rescore_kernel  <<<N_ROWS, 256>>>(x, Ae);
    decode_kernel   <<<N_ROWS, 256>>>(bd, out);
}

// round 15
// speedup vs baseline: 1.4700x; 1.2550x over previous
#include <cuda_runtime.h>
#include <cuda_bf16.h>
#include <cstdint>

#define N_ROWS 8192
#define D_DIM  768
#define W_DIM  24576
#define K_TOP  64
#define NCAP   256     // candidate capacity
#define NSORT  256
#define THR_RANK  96u  // bf16 rank boundary for candidate admission
#define THR_SLACK 4u   // bf16-key ulps of threshold slack

// ---------------- scratch (device globals) ---------------------------------
__device__ __align__(16) __nv_bfloat16 g_xb [(size_t)N_ROWS * D_DIM];
__device__ __align__(16) __nv_bfloat16 g_aeb[(size_t)W_DIM * D_DIM];
__device__ __align__(16) __nv_bfloat16 g_preb[(size_t)N_ROWS * W_DIM];   // 402 MB
__device__ __align__(16) float g_AdT[(size_t)W_DIM * D_DIM];             // 75 MB
__device__ float g_beff[W_DIM];
__device__ int   g_cand[(size_t)N_ROWS * NCAP];
__device__ int   g_candcnt[N_ROWS];
__device__ float g_vals[N_ROWS * K_TOP];
__device__ int   g_idx [N_ROWS * K_TOP];

// ---------------- helpers ----------------------------------------------------
__device__ __forceinline__ uint32_t smem_u32(const void* p) {
    uint32_t a;
    asm("{ .reg .u64 t; cvta.to.shared.u64 t, %1; cvt.u32.u64 %0, t; }"
        : "=r"(a) : "l"(p));
    return a;
}
#define CP16(sa, g) asm volatile("cp.async.cg.shared.global [%0], [%1], 16;" :: "r"(sa), "l"(g))
#define CP_COMMIT() asm volatile("cp.async.commit_group;" ::: "memory")
#define CP_WAIT3()  asm volatile("cp.async.wait_group 3;" ::: "memory")

#define LDSM4(r0, r1, r2, r3, a) \
    asm volatile("ldmatrix.sync.aligned.m8n8.x4.shared.b16 {%0,%1,%2,%3}, [%4];" \
                 : "=r"(r0), "=r"(r1), "=r"(r2), "=r"(r3) : "r"(a))

__device__ __forceinline__ void mma16816(float* c, const uint32_t* a, const uint32_t* b) {
    asm volatile("mma.sync.aligned.m16n8k16.row.col.f32.bf16.bf16.f32 "
                 "{%0,%1,%2,%3}, {%4,%5,%6,%7}, {%8,%9}, {%0,%1,%2,%3};"
                 : "+f"(c[0]), "+f"(c[1]), "+f"(c[2]), "+f"(c[3])
                 : "r"(a[0]), "r"(a[1]), "r"(a[2]), "r"(a[3]), "r"(b[0]), "r"(b[1]));
}

// ---------------- fused fp32 -> bf16 convert (x then Ae) --------------------
__global__ __launch_bounds__(256) void cvt_all_kernel(const float* __restrict__ x,
                                                      const float* __restrict__ Ae) {
    const int nx4  = N_ROWS * D_DIM / 4;
    const int nae4 = W_DIM * D_DIM / 4;
    int i = blockIdx.x * 256 + threadIdx.x;
    const float* src;
    __nv_bfloat16* dst;
    int j;
    if (i < nx4)              { src = x;  dst = g_xb;  j = i; }
    else if (i < nx4 + nae4)  { src = Ae; dst = g_aeb; j = i - nx4; }
    else return;
    float4 v = ((const float4*)src)[j];
    uint32_t p0, p1;
    asm("cvt.rn.bf16x2.f32 %0, %1, %2;" : "=r"(p0) : "f"(v.y), "f"(v.x));
    asm("cvt.rn.bf16x2.f32 %0, %1, %2;" : "=r"(p1) : "f"(v.w), "f"(v.z));
    ((uint2*)dst)[j] = make_uint2(p0, p1);
}

// ---------------- beff[w] = be[w] - dot(bd, Ae[w,:]) ------------------------
__global__ __launch_bounds__(256) void beff_kernel(const float* __restrict__ be,
                                                   const float* __restrict__ bd,
                                                   const float* __restrict__ Ae) {
    int w    = blockIdx.x * 8 + (threadIdx.x >> 5);
    int lane = threadIdx.x & 31;
    const float* row = Ae + (size_t)w * D_DIM;
    float s = 0.f;
    for (int d = lane; d < D_DIM; d += 32) s += bd[d] * row[d];
    #pragma unroll
    for (int o = 16; o > 0; o >>= 1) s += __shfl_down_sync(0xffffffffu, s, o);
    if (lane == 0) g_beff[w] = be[w] - s;
}

// ---------------- AdT[w,d] = Ad[d,w] ----------------------------------------
__global__ __launch_bounds__(256) void transpose_kernel(const float* __restrict__ Ad) {
    __shared__ float tile[32][33];
    int w0 = blockIdx.x * 32;
    int d0 = blockIdx.y * 32;
    int tx = threadIdx.x, ty = threadIdx.y;   // 32 x 8
    #pragma unroll
    for (int i = 0; i < 32; i += 8)
        tile[ty + i][tx] = Ad[(size_t)(d0 + ty + i) * W_DIM + w0 + tx];
    __syncthreads();
    #pragma unroll
    for (int i = 0; i < 32; i += 8)
        g_AdT[(size_t)(w0 + ty + i) * D_DIM + d0 + tx] = tile[tx][ty + i];
}

// ---------------- bf16 HMMA GEMM: preb = Xb @ Aeb^T + beff -------------------
// FROZEN at R11 best: 128x128 CTA, BK=32, 5-stage cp.async, warp 64x32,
// 2 CTAs/SM, one barrier per mainloop iteration.
#define GBK     32
#define NSTAGE  5
#define ROWPITCH 80
#define ASTAGE  (128 * ROWPITCH)
#define STAGEB  (2 * ASTAGE)              // 20480
#define KT      (D_DIM / GBK)             // 24

__global__ __launch_bounds__(256, 2) void gemm_kernel() {
    extern __shared__ char smem[];
    const uint32_t SB = (smem_u32(smem) + 127u) & ~127u;
    const int tid  = threadIdx.x;
    const int wid  = tid >> 5;
    const int lane = tid & 31;
    const int wm   = wid & 1;
    const int wn   = wid >> 1;

    const __nv_bfloat16* Ag = g_xb  + (size_t)(blockIdx.y * 128) * D_DIM;
    const __nv_bfloat16* Bg = g_aeb + (size_t)(blockIdx.x * 128) * D_DIM;

    const int lrow = tid >> 2;
    const int lcol = tid & 3;

    auto load_stage = [&](int s, int k0) {
        const uint32_t ab = SB + s * STAGEB;
        const uint32_t bb = ab + ASTAGE;
        #pragma unroll
        for (int h = 0; h < 2; ++h) {
            int r = lrow + h * 64;
            CP16(ab + r * ROWPITCH + lcol * 16, Ag + (size_t)r * D_DIM + k0 + lcol * 8);
            CP16(bb + r * ROWPITCH + lcol * 16, Bg + (size_t)r * D_DIM + k0 + lcol * 8);
        }
    };

    float acc[4][4][4];
    #pragma unroll
    for (int i = 0; i < 4; ++i)
        #pragma unroll
        for (int j = 0; j < 4; ++j)
            #pragma unroll
            for (int q = 0; q < 4; ++q) acc[i][j][q] = 0.f;

    load_stage(0, 0);  CP_COMMIT();
    load_stage(1, 32); CP_COMMIT();
    load_stage(2, 64); CP_COMMIT();
    load_stage(3, 96); CP_COMMIT();

    const int a_row = (lane & 15);
    const int a_kb  = (lane >> 4) * 16;
    const int b_row = ((lane >> 4) & 1) * 8 + (lane & 7);
    const int b_kb  = ((lane >> 3) & 1) * 16;

    for (int it = 0; it < KT; ++it) {
        CP_WAIT3();
        __syncthreads();
        {
            int nx = it + 4;
            if (nx < KT) load_stage(nx % NSTAGE, nx * GBK);
            CP_COMMIT();
        }

        const uint32_t ab = SB + (it % NSTAGE) * STAGEB;
        const uint32_t bb = ab + ASTAGE;
        #pragma unroll
        for (int ks = 0; ks < 2; ++ks) {
            uint32_t af[4][4], bf[2][4];
            #pragma unroll
            for (int mt = 0; mt < 4; ++mt) {
                uint32_t addr = ab + (wm * 64 + mt * 16 + a_row) * ROWPITCH
                              + a_kb + ks * 32;
                LDSM4(af[mt][0], af[mt][1], af[mt][2], af[mt][3], addr);
            }
            #pragma unroll
            for (int bt = 0; bt < 2; ++bt) {
                uint32_t addr = bb + (wn * 32 + bt * 16 + b_row) * ROWPITCH
                              + b_kb + ks * 32;
                LDSM4(bf[bt][0], bf[bt][1], bf[bt][2], bf[bt][3], addr);
            }
            #pragma unroll
            for (int mt = 0; mt < 4; ++mt)
                #pragma unroll
                for (int nt = 0; nt < 4; ++nt)
                    mma16816(acc[mt][nt], af[mt], &bf[nt >> 1][(nt & 1) * 2]);
        }
    }

    const int g  = lane >> 2;
    const int tg = lane & 3;
    const int rowBase = blockIdx.y * 128 + wm * 64;
    const int colBase = blockIdx.x * 128 + wn * 32;
    #pragma unroll
    for (int nt = 0; nt < 4; ++nt) {
        const int c = colBase + nt * 8 + tg * 2;
        const float bz0 = g_beff[c], bz1 = g_beff[c + 1];
        #pragma unroll
        for (int mt = 0; mt < 4; ++mt) {
            const int r0 = rowBase + mt * 16 + g;
            uint32_t p0, p1;
            float v00 = acc[mt][nt][0] + bz0, v01 = acc[mt][nt][1] + bz1;
            float v10 = acc[mt][nt][2] + bz0, v11 = acc[mt][nt][3] + bz1;
            asm("cvt.rn.bf16x2.f32 %0, %1, %2;" : "=r"(p0) : "f"(v01), "f"(v00));
            asm("cvt.rn.bf16x2.f32 %0, %1, %2;" : "=r"(p1) : "f"(v11), "f"(v10));
            *(uint32_t*)(g_preb + (size_t)r0 * W_DIM + c)       = p0;
            *(uint32_t*)(g_preb + (size_t)(r0 + 8) * W_DIM + c) = p1;
        }
    }
}

// ---------------- per-row candidate select (bf16 keys) ----------------------
// Level-1: per-warp private histograms, plain atomics (no match_any).
// Level-2: direct atomics, boundary-bin items only.
__global__ __launch_bounds__(256) void topk_kernel() {
    extern __shared__ uint16_t sk[];          // W_DIM keys (48KB)
    __shared__ uint32_t whist[8][256];        // per-warp level-1 hists (8KB)
    __shared__ uint32_t hist[256];
    __shared__ uint32_t s_b1, s_need, s_thr, s_cnt;

    const int tid = threadIdx.x;
    const int wid = tid >> 5;
    const int row = blockIdx.x;
    const uint4* src = (const uint4*)(g_preb + (size_t)row * W_DIM);

    #pragma unroll
    for (int i = 0; i < 8; ++i) whist[i][tid] = 0u;
    if (tid == 0) s_cnt = 0u;
    __syncthreads();

    // pass 1: convert to order-preserving u16 keys + per-warp level-1 histogram
    uint32_t* myh = whist[wid];
    for (int i = tid; i < W_DIM / 8; i += 256) {
        uint4 v = src[i];
        uint32_t w[4] = {v.x, v.y, v.z, v.w};
        #pragma unroll
        for (int q = 0; q < 4; ++q) {
            uint16_t lo = (uint16_t)(w[q] & 0xFFFF), hi = (uint16_t)(w[q] >> 16);
            uint16_t k0 = (lo & 0x8000) ? (uint16_t)~lo : (uint16_t)(lo | 0x8000);
            uint16_t k1 = (hi & 0x8000) ? (uint16_t)~hi : (uint16_t)(hi | 0x8000);
            sk[i * 8 + q * 2 + 0] = k0;
            sk[i * 8 + q * 2 + 1] = k1;
            atomicAdd(&myh[k0 >> 8], 1u);
            atomicAdd(&myh[k1 >> 8], 1u);
        }
    }
    __syncthreads();
    // reduce per-warp hists
    {
        uint32_t s = 0u;
        #pragma unroll
        for (int wq = 0; wq < 8; ++wq) s += whist[wq][tid];
        hist[tid] = s;
    }
    __syncthreads();
    if (tid == 0) {
        uint32_t cum = 0u; int b1 = 0;
        for (int b = 255; b >= 0; --b) {
            if (cum + hist[b] >= THR_RANK) { b1 = b; break; }
            cum += hist[b];
        }
        s_b1 = (uint32_t)b1; s_need = THR_RANK - cum;
    }
    __syncthreads();
    const uint32_t b1 = s_b1;
    hist[tid] = 0u;
    __syncthreads();

    // level 2: low byte within boundary bin b1 (sparse -> direct atomics)
    for (int i = tid; i < W_DIM; i += 256) {
        uint16_t u = sk[i];
        if ((uint32_t)(u >> 8) == b1) atomicAdd(&hist[u & 0xFF], 1u);
    }
    __syncthreads();
    if (tid == 0) {
        uint32_t need = s_need, cum = 0u; int b2 = 0;
        for (int b = 255; b >= 0; --b) {
            if (cum + hist[b] >= need) { b2 = b; break; }
            cum += hist[b];
        }
        uint32_t thr = (b1 << 8) | (uint32_t)b2;
        s_thr = (thr > THR_SLACK) ? thr - THR_SLACK : 0u;
    }
    __syncthreads();
    const uint32_t thr = s_thr;
    int* crow = g_cand + (size_t)row * NCAP;

    // admit ALL items with key >= thr (deterministic superset of bf16 top-96)
    for (int i = tid; i < W_DIM; i += 256) {
        if ((uint32_t)sk[i] >= thr) {
            int pos = (int)atomicAdd(&s_cnt, 1u);
            if (pos < NCAP) crow[pos] = i;
        }
    }
    __syncthreads();
    if (tid == 0) g_candcnt[row] = (s_cnt < NCAP) ? (int)s_cnt : NCAP;
}

// ---------------- exact fp32 rescore: ONE THREAD PER CANDIDATE --------------
// FROZEN accumulation order: ascending-k scalar fmaf chain (matches reference).
__global__ __launch_bounds__(256) void rescore_kernel(const float* __restrict__ x,
                                                      const float* __restrict__ Ae) {
    __shared__ __align__(16) float sx[D_DIM];
    __shared__ unsigned long long skey[NSORT];

    const int tid = threadIdx.x, row = blockIdx.x;
    const int cnt = g_candcnt[row];
    for (int i = tid; i < D_DIM / 4; i += 256)
        ((float4*)sx)[i] = ((const float4*)(x + (size_t)row * D_DIM))[i];
    skey[tid] = 0ull;
    __syncthreads();

    if (tid < cnt) {
        const int c = g_cand[(size_t)row * NCAP + tid];
        const float4* ar = (const float4*)(Ae + (size_t)c * D_DIM);
        const float4* xr = (const float4*)sx;
        float acc = 0.f;
        #pragma unroll 4
        for (int q = 0; q < D_DIM / 4; ++q) {        // ascending k, scalar chain
            float4 a = ar[q], b = xr[q];
            acc = fmaf(a.x, b.x, acc);
            acc = fmaf(a.y, b.y, acc);
            acc = fmaf(a.z, b.z, acc);
            acc = fmaf(a.w, b.w, acc);
        }
        float v = acc + g_beff[c];
        uint32_t bbits = __float_as_uint(v);
        uint32_t fk = (bbits & 0x80000000u) ? ~bbits : (bbits | 0x80000000u);
        skey[tid] = ((unsigned long long)fk << 32) | (uint32_t)(~(uint32_t)c);
    }
    __syncthreads();

    // bitonic sort (desc by val, ties: smaller idx first)
    for (int k = 2; k <= NSORT; k <<= 1) {
        for (int jj = k >> 1; jj > 0; jj >>= 1) {
            int p = tid ^ jj;
            if (p > tid) {
                bool up = ((tid & k) == 0);
                unsigned long long a = skey[tid], b = skey[p];
                bool sw = up ? (a < b) : (a > b);
                if (sw) { skey[tid] = b; skey[p] = a; }
            }
            __syncthreads();
        }
    }
    if (tid < K_TOP) {
        unsigned long long kk = skey[tid];
        uint32_t fk = (uint32_t)(kk >> 32);
        uint32_t b  = (fk & 0x80000000u) ? (fk ^ 0x80000000u) : ~fk;
        g_vals[row * K_TOP + tid] = fmaxf(__uint_as_float(b), 0.f);
        g_idx [row * K_TOP + tid] = (int)(~(uint32_t)kk);
    }
}

// ---------------- decode: out[n,:] = sum_j v_j * AdT[i_j,:] + bd -------------
__global__ __launch_bounds__(256) void decode_kernel(const float* __restrict__ bd,
                                                     float* __restrict__ out) {
    __shared__ float         sv[K_TOP];
    __shared__ const float4* sp[K_TOP];
    const int row = blockIdx.x;
    const int tid = threadIdx.x;
    if (tid < K_TOP) {
        sv[tid] = g_vals[row * K_TOP + tid];
        sp[tid] = (const float4*)(g_AdT + (size_t)g_idx[row * K_TOP + tid] * D_DIM);
    }
    __syncthreads();
    if (tid < D_DIM / 4) {
        float4 acc = ((const float4*)bd)[tid];
        #pragma unroll 8
        for (int j = 0; j < K_TOP; ++j) {
            float4 a = sp[j][tid];
            float  v = sv[j];
            acc.x = fmaf(v, a.x, acc.x);
            acc.y = fmaf(v, a.y, acc.y);
            acc.z = fmaf(v, a.z, acc.z);
            acc.w = fmaf(v, a.w, acc.w);
        }
        ((float4*)(out + (size_t)row * D_DIM))[tid] = acc;
    }
}

// ---------------- launch -----------------------------------------------------
extern "C" void kernel_launch(void* const* d_in, const int* in_sizes, int n_in,
                              void* d_out, int out_size) {
    const float* x  = (const float*)d_in[0];
    const float* Ae = (const float*)d_in[1];
    const float* be = (const float*)d_in[2];
    const float* Ad = (const float*)d_in[3];
    const float* bd = (const float*)d_in[4];
    float* out = (float*)d_out;

    const int gemm_smem = NSTAGE * STAGEB + 256;      // ~102.6 KB -> 2 CTAs/SM
    cudaFuncSetAttribute(gemm_kernel, cudaFuncAttributeMaxDynamicSharedMemorySize, gemm_smem);
    const int topk_smem = W_DIM * (int)sizeof(uint16_t);   // 48 KB dynamic
    cudaFuncSetAttribute(topk_kernel, cudaFuncAttributeMaxDynamicSharedMemorySize, topk_smem);

    const int ncvt = (N_ROWS * D_DIM + W_DIM * D_DIM) / 4;

    // topk is the 4th launch -> lands at ncu's capture slot
    cvt_all_kernel  <<<(ncvt + 255) / 256, 256>>>(x, Ae);
    beff_kernel     <<<W_DIM / 8, 256>>>(be, bd, Ae);
    gemm_kernel     <<<dim3(W_DIM / 128, N_ROWS / 128), 256, gemm_smem>>>();
    topk_kernel     <<<N_ROWS, 256, topk_smem>>>();
    transpose_kernel<<<dim3(W_DIM / 32, D_DIM / 32), dim3(32, 8)>>>(Ad);
    rescore_kernel  <<<N_ROWS, 256>>>(x, Ae);
    decode_kernel   <<<N_ROWS, 256>>>(bd, out);
}

// round 16
// speedup vs baseline: 1.5015x; 1.0214x over previous
#include <cuda_runtime.h>
#include <cuda_bf16.h>
#include <cstdint>

#define N_ROWS 8192
#define D_DIM  768
#define W_DIM  24576
#define K_TOP  64
#define NCAP   256     // candidate capacity
#define NSORT  256
#define THR_RANK  96u  // bf16 rank boundary for candidate admission
#define THR_SLACK 4u   // bf16-key ulps of threshold slack

// ---------------- scratch (device globals) ---------------------------------
__device__ __align__(16) __nv_bfloat16 g_xb [(size_t)N_ROWS * D_DIM];
__device__ __align__(16) __nv_bfloat16 g_aeb[(size_t)W_DIM * D_DIM];
__device__ __align__(16) __nv_bfloat16 g_preb[(size_t)N_ROWS * W_DIM];   // 402 MB
__device__ __align__(16) float g_AdT[(size_t)W_DIM * D_DIM];             // 75 MB
__device__ float g_beff[W_DIM];
__device__ int   g_cand[(size_t)N_ROWS * NCAP];
__device__ int   g_candcnt[N_ROWS];
__device__ float g_vals[N_ROWS * K_TOP];
__device__ int   g_idx [N_ROWS * K_TOP];

// ---------------- helpers ----------------------------------------------------
__device__ __forceinline__ uint32_t smem_u32(const void* p) {
    uint32_t a;
    asm("{ .reg .u64 t; cvta.to.shared.u64 t, %1; cvt.u32.u64 %0, t; }"
        : "=r"(a) : "l"(p));
    return a;
}
#define CP16(sa, g) asm volatile("cp.async.cg.shared.global [%0], [%1], 16;" :: "r"(sa), "l"(g))
#define CP_COMMIT() asm volatile("cp.async.commit_group;" ::: "memory")
#define CP_WAIT3()  asm volatile("cp.async.wait_group 3;" ::: "memory")

#define LDSM4(r0, r1, r2, r3, a) \
    asm volatile("ldmatrix.sync.aligned.m8n8.x4.shared.b16 {%0,%1,%2,%3}, [%4];" \
                 : "=r"(r0), "=r"(r1), "=r"(r2), "=r"(r3) : "r"(a))

__device__ __forceinline__ void mma16816(float* c, const uint32_t* a, const uint32_t* b) {
    asm volatile("mma.sync.aligned.m16n8k16.row.col.f32.bf16.bf16.f32 "
                 "{%0,%1,%2,%3}, {%4,%5,%6,%7}, {%8,%9}, {%0,%1,%2,%3};"
                 : "+f"(c[0]), "+f"(c[1]), "+f"(c[2]), "+f"(c[3])
                 : "r"(a[0]), "r"(a[1]), "r"(a[2]), "r"(a[3]), "r"(b[0]), "r"(b[1]));
}

// ---------------- fused fp32 -> bf16 convert (x then Ae) --------------------
__global__ __launch_bounds__(256) void cvt_all_kernel(const float* __restrict__ x,
                                                      const float* __restrict__ Ae) {
    const int nx4  = N_ROWS * D_DIM / 4;
    const int nae4 = W_DIM * D_DIM / 4;
    int i = blockIdx.x * 256 + threadIdx.x;
    const float* src;
    __nv_bfloat16* dst;
    int j;
    if (i < nx4)              { src = x;  dst = g_xb;  j = i; }
    else if (i < nx4 + nae4)  { src = Ae; dst = g_aeb; j = i - nx4; }
    else return;
    float4 v = ((const float4*)src)[j];
    uint32_t p0, p1;
    asm("cvt.rn.bf16x2.f32 %0, %1, %2;" : "=r"(p0) : "f"(v.y), "f"(v.x));
    asm("cvt.rn.bf16x2.f32 %0, %1, %2;" : "=r"(p1) : "f"(v.w), "f"(v.z));
    ((uint2*)dst)[j] = make_uint2(p0, p1);
}

// ---------------- beff[w] = be[w] - dot(bd, Ae[w,:]) ------------------------
__global__ __launch_bounds__(256) void beff_kernel(const float* __restrict__ be,
                                                   const float* __restrict__ bd,
                                                   const float* __restrict__ Ae) {
    int w    = blockIdx.x * 8 + (threadIdx.x >> 5);
    int lane = threadIdx.x & 31;
    const float* row = Ae + (size_t)w * D_DIM;
    float s = 0.f;
    for (int d = lane; d < D_DIM; d += 32) s += bd[d] * row[d];
    #pragma unroll
    for (int o = 16; o > 0; o >>= 1) s += __shfl_down_sync(0xffffffffu, s, o);
    if (lane == 0) g_beff[w] = be[w] - s;
}

// ---------------- AdT[w,d] = Ad[d,w] ----------------------------------------
__global__ __launch_bounds__(256) void transpose_kernel(const float* __restrict__ Ad) {
    __shared__ float tile[32][33];
    int w0 = blockIdx.x * 32;
    int d0 = blockIdx.y * 32;
    int tx = threadIdx.x, ty = threadIdx.y;   // 32 x 8
    #pragma unroll
    for (int i = 0; i < 32; i += 8)
        tile[ty + i][tx] = Ad[(size_t)(d0 + ty + i) * W_DIM + w0 + tx];
    __syncthreads();
    #pragma unroll
    for (int i = 0; i < 32; i += 8)
        g_AdT[(size_t)(w0 + ty + i) * D_DIM + d0 + tx] = tile[tx][ty + i];
}

// ---------------- bf16 HMMA GEMM: preb = Xb @ Aeb^T + beff -------------------
// FROZEN at R11 best: 128x128 CTA, BK=32, 5-stage cp.async, warp 64x32,
// 2 CTAs/SM, one barrier per mainloop iteration.
#define GBK     32
#define NSTAGE  5
#define ROWPITCH 80
#define ASTAGE  (128 * ROWPITCH)
#define STAGEB  (2 * ASTAGE)              // 20480
#define KT      (D_DIM / GBK)             // 24

__global__ __launch_bounds__(256, 2) void gemm_kernel() {
    extern __shared__ char smem[];
    const uint32_t SB = (smem_u32(smem) + 127u) & ~127u;
    const int tid  = threadIdx.x;
    const int wid  = tid >> 5;
    const int lane = tid & 31;
    const int wm   = wid & 1;
    const int wn   = wid >> 1;

    const __nv_bfloat16* Ag = g_xb  + (size_t)(blockIdx.y * 128) * D_DIM;
    const __nv_bfloat16* Bg = g_aeb + (size_t)(blockIdx.x * 128) * D_DIM;

    const int lrow = tid >> 2;
    const int lcol = tid & 3;

    auto load_stage = [&](int s, int k0) {
        const uint32_t ab = SB + s * STAGEB;
        const uint32_t bb = ab + ASTAGE;
        #pragma unroll
        for (int h = 0; h < 2; ++h) {
            int r = lrow + h * 64;
            CP16(ab + r * ROWPITCH + lcol * 16, Ag + (size_t)r * D_DIM + k0 + lcol * 8);
            CP16(bb + r * ROWPITCH + lcol * 16, Bg + (size_t)r * D_DIM + k0 + lcol * 8);
        }
    };

    float acc[4][4][4];
    #pragma unroll
    for (int i = 0; i < 4; ++i)
        #pragma unroll
        for (int j = 0; j < 4; ++j)
            #pragma unroll
            for (int q = 0; q < 4; ++q) acc[i][j][q] = 0.f;

    load_stage(0, 0);  CP_COMMIT();
    load_stage(1, 32); CP_COMMIT();
    load_stage(2, 64); CP_COMMIT();
    load_stage(3, 96); CP_COMMIT();

    const int a_row = (lane & 15);
    const int a_kb  = (lane >> 4) * 16;
    const int b_row = ((lane >> 4) & 1) * 8 + (lane & 7);
    const int b_kb  = ((lane >> 3) & 1) * 16;

    for (int it = 0; it < KT; ++it) {
        CP_WAIT3();
        __syncthreads();
        {
            int nx = it + 4;
            if (nx < KT) load_stage(nx % NSTAGE, nx * GBK);
            CP_COMMIT();
        }

        const uint32_t ab = SB + (it % NSTAGE) * STAGEB;
        const uint32_t bb = ab + ASTAGE;
        #pragma unroll
        for (int ks = 0; ks < 2; ++ks) {
            uint32_t af[4][4], bf[2][4];
            #pragma unroll
            for (int mt = 0; mt < 4; ++mt) {
                uint32_t addr = ab + (wm * 64 + mt * 16 + a_row) * ROWPITCH
                              + a_kb + ks * 32;
                LDSM4(af[mt][0], af[mt][1], af[mt][2], af[mt][3], addr);
            }
            #pragma unroll
            for (int bt = 0; bt < 2; ++bt) {
                uint32_t addr = bb + (wn * 32 + bt * 16 + b_row) * ROWPITCH
                              + b_kb + ks * 32;
                LDSM4(bf[bt][0], bf[bt][1], bf[bt][2], bf[bt][3], addr);
            }
            #pragma unroll
            for (int mt = 0; mt < 4; ++mt)
                #pragma unroll
                for (int nt = 0; nt < 4; ++nt)
                    mma16816(acc[mt][nt], af[mt], &bf[nt >> 1][(nt & 1) * 2]);
        }
    }

    const int g  = lane >> 2;
    const int tg = lane & 3;
    const int rowBase = blockIdx.y * 128 + wm * 64;
    const int colBase = blockIdx.x * 128 + wn * 32;
    #pragma unroll
    for (int nt = 0; nt < 4; ++nt) {
        const int c = colBase + nt * 8 + tg * 2;
        const float bz0 = g_beff[c], bz1 = g_beff[c + 1];
        #pragma unroll
        for (int mt = 0; mt < 4; ++mt) {
            const int r0 = rowBase + mt * 16 + g;
            uint32_t p0, p1;
            float v00 = acc[mt][nt][0] + bz0, v01 = acc[mt][nt][1] + bz1;
            float v10 = acc[mt][nt][2] + bz0, v11 = acc[mt][nt][3] + bz1;
            asm("cvt.rn.bf16x2.f32 %0, %1, %2;" : "=r"(p0) : "f"(v01), "f"(v00));
            asm("cvt.rn.bf16x2.f32 %0, %1, %2;" : "=r"(p1) : "f"(v11), "f"(v10));
            *(uint32_t*)(g_preb + (size_t)r0 * W_DIM + c)       = p0;
            *(uint32_t*)(g_preb + (size_t)(r0 + 8) * W_DIM + c) = p1;
        }
    }
}

// ---------------- per-row candidate select: REGISTER-RESIDENT keys ----------
// 96 u16 keys/thread packed in 48 u32 regs; no smem key staging.
// Same thresholds/semantics as R15 -> bit-identical candidate set.
__global__ __launch_bounds__(256) void topk_kernel() {
    __shared__ uint32_t whist[8][256];        // per-warp level-1 hists (8KB)
    __shared__ uint32_t hist[256];
    __shared__ uint32_t s_b1, s_need, s_thr, s_cnt;

    const int tid = threadIdx.x;
    const int wid = tid >> 5;
    const int row = blockIdx.x;
    const uint4* src = (const uint4*)(g_preb + (size_t)row * W_DIM);

    #pragma unroll
    for (int i = 0; i < 8; ++i) whist[i][tid] = 0u;
    if (tid == 0) s_cnt = 0u;
    __syncthreads();

    // pass 1: load + convert to order-preserving u16 keys (registers) + hist
    uint32_t keys[48];
    uint32_t* myh = whist[wid];
    #pragma unroll
    for (int it = 0; it < 12; ++it) {
        uint4 v = src[tid + it * 256];
        uint32_t w[4] = {v.x, v.y, v.z, v.w};
        #pragma unroll
        for (int q = 0; q < 4; ++q) {
            uint32_t x = w[q];
            uint16_t lo = (uint16_t)x, hi = (uint16_t)(x >> 16);
            uint32_t k0 = (lo & 0x8000) ? (uint32_t)(uint16_t)~lo : (uint32_t)(lo | 0x8000);
            uint32_t k1 = (hi & 0x8000) ? (uint32_t)(uint16_t)~hi : (uint32_t)(hi | 0x8000);
            keys[it * 4 + q] = k0 | (k1 << 16);
            atomicAdd(&myh[k0 >> 8], 1u);
            atomicAdd(&myh[k1 >> 8], 1u);
        }
    }
    __syncthreads();
    // reduce per-warp hists
    {
        uint32_t s = 0u;
        #pragma unroll
        for (int wq = 0; wq < 8; ++wq) s += whist[wq][tid];
        hist[tid] = s;
    }
    __syncthreads();
    if (tid == 0) {
        uint32_t cum = 0u; int b1 = 0;
        for (int b = 255; b >= 0; --b) {
            if (cum + hist[b] >= THR_RANK) { b1 = b; break; }
            cum += hist[b];
        }
        s_b1 = (uint32_t)b1; s_need = THR_RANK - cum;
    }
    __syncthreads();
    const uint32_t b1 = s_b1;
    hist[tid] = 0u;
    __syncthreads();

    // level 2: scan register keys; boundary-bin items only (rare)
    #pragma unroll
    for (int j = 0; j < 48; ++j) {
        uint32_t k = keys[j];
        uint32_t lo = k & 0xFFFFu, hi = k >> 16;
        if ((lo >> 8) == b1) atomicAdd(&hist[lo & 0xFF], 1u);
        if ((hi >> 8) == b1) atomicAdd(&hist[hi & 0xFF], 1u);
    }
    __syncthreads();
    if (tid == 0) {
        uint32_t need = s_need, cum = 0u; int b2 = 0;
        for (int b = 255; b >= 0; --b) {
            if (cum + hist[b] >= need) { b2 = b; break; }
            cum += hist[b];
        }
        uint32_t thr = (b1 << 8) | (uint32_t)b2;
        s_thr = (thr > THR_SLACK) ? thr - THR_SLACK : 0u;
    }
    __syncthreads();
    const uint32_t thr = s_thr;
    int* crow = g_cand + (size_t)row * NCAP;

    // admission: scan register keys, emit global indices
    #pragma unroll
    for (int it = 0; it < 12; ++it) {
        #pragma unroll
        for (int q = 0; q < 4; ++q) {
            uint32_t k = keys[it * 4 + q];
            uint32_t lo = k & 0xFFFFu, hi = k >> 16;
            if (lo >= thr || hi >= thr) {
                const int base = (tid + it * 256) * 8 + q * 2;
                if (lo >= thr) {
                    int pos = (int)atomicAdd(&s_cnt, 1u);
                    if (pos < NCAP) crow[pos] = base;
                }
                if (hi >= thr) {
                    int pos = (int)atomicAdd(&s_cnt, 1u);
                    if (pos < NCAP) crow[pos] = base + 1;
                }
            }
        }
    }
    __syncthreads();
    if (tid == 0) g_candcnt[row] = (s_cnt < NCAP) ? (int)s_cnt : NCAP;
}

// ---------------- exact fp32 rescore: ONE THREAD PER CANDIDATE --------------
// FROZEN accumulation order: ascending-k scalar fmaf chain (matches reference).
__global__ __launch_bounds__(256) void rescore_kernel(const float* __restrict__ x,
                                                      const float* __restrict__ Ae) {
    __shared__ __align__(16) float sx[D_DIM];
    __shared__ unsigned long long skey[NSORT];

    const int tid = threadIdx.x, row = blockIdx.x;
    const int cnt = g_candcnt[row];
    for (int i = tid; i < D_DIM / 4; i += 256)
        ((float4*)sx)[i] = ((const float4*)(x + (size_t)row * D_DIM))[i];
    skey[tid] = 0ull;
    __syncthreads();

    if (tid < cnt) {
        const int c = g_cand[(size_t)row * NCAP + tid];
        const float4* ar = (const float4*)(Ae + (size_t)c * D_DIM);
        const float4* xr = (const float4*)sx;
        float acc = 0.f;
        #pragma unroll 4
        for (int q = 0; q < D_DIM / 4; ++q) {        // ascending k, scalar chain
            float4 a = ar[q], b = xr[q];
            acc = fmaf(a.x, b.x, acc);
            acc = fmaf(a.y, b.y, acc);
            acc = fmaf(a.z, b.z, acc);
            acc = fmaf(a.w, b.w, acc);
        }
        float v = acc + g_beff[c];
        uint32_t bbits = __float_as_uint(v);
        uint32_t fk = (bbits & 0x80000000u) ? ~bbits : (bbits | 0x80000000u);
        skey[tid] = ((unsigned long long)fk << 32) | (uint32_t)(~(uint32_t)c);
    }
    __syncthreads();

    // bitonic sort (desc by val, ties: smaller idx first)
    for (int k = 2; k <= NSORT; k <<= 1) {
        for (int jj = k >> 1; jj > 0; jj >>= 1) {
            int p = tid ^ jj;
            if (p > tid) {
                bool up = ((tid & k) == 0);
                unsigned long long a = skey[tid], b = skey[p];
                bool sw = up ? (a < b) : (a > b);
                if (sw) { skey[tid] = b; skey[p] = a; }
            }
            __syncthreads();
        }
    }
    if (tid < K_TOP) {
        unsigned long long kk = skey[tid];
        uint32_t fk = (uint32_t)(kk >> 32);
        uint32_t b  = (fk & 0x80000000u) ? (fk ^ 0x80000000u) : ~fk;
        g_vals[row * K_TOP + tid] = fmaxf(__uint_as_float(b), 0.f);
        g_idx [row * K_TOP + tid] = (int)(~(uint32_t)kk);
    }
}

// ---------------- decode: out[n,:] = sum_j v_j * AdT[i_j,:] + bd -------------
__global__ __launch_bounds__(256) void decode_kernel(const float* __restrict__ bd,
                                                     float* __restrict__ out) {
    __shared__ float         sv[K_TOP];
    __shared__ const float4* sp[K_TOP];
    const int row = blockIdx.x;
    const int tid = threadIdx.x;
    if (tid < K_TOP) {
        sv[tid] = g_vals[row * K_TOP + tid];
        sp[tid] = (const float4*)(g_AdT + (size_t)g_idx[row * K_TOP + tid] * D_DIM);
    }
    __syncthreads();
    if (tid < D_DIM / 4) {
        float4 acc = ((const float4*)bd)[tid];
        #pragma unroll 16
        for (int j = 0; j < K_TOP; ++j) {
            float4 a = sp[j][tid];
            float  v = sv[j];
            acc.x = fmaf(v, a.x, acc.x);
            acc.y = fmaf(v, a.y, acc.y);
            acc.z = fmaf(v, a.z, acc.z);
            acc.w = fmaf(v, a.w, acc.w);
        }
        ((float4*)(out + (size_t)row * D_DIM))[tid] = acc;
    }
}

// ---------------- launch -----------------------------------------------------
extern "C" void kernel_launch(void* const* d_in, const int* in_sizes, int n_in,
                              void* d_out, int out_size) {
    const float* x  = (const float*)d_in[0];
    const float* Ae = (const float*)d_in[1];
    const float* be = (const float*)d_in[2];
    const float* Ad = (const float*)d_in[3];
    const float* bd = (const float*)d_in[4];
    float* out = (float*)d_out;

    const int gemm_smem = NSTAGE * STAGEB + 256;      // ~102.6 KB -> 2 CTAs/SM
    cudaFuncSetAttribute(gemm_kernel, cudaFuncAttributeMaxDynamicSharedMemorySize, gemm_smem);

    const int ncvt = (N_ROWS * D_DIM + W_DIM * D_DIM) / 4;

    // topk is the 4th launch -> lands at ncu's capture slot
    cvt_all_kernel  <<<(ncvt + 255) / 256, 256>>>(x, Ae);
    beff_kernel     <<<W_DIM / 8, 256>>>(be, bd, Ae);
    gemm_kernel     <<<dim3(W_DIM / 128, N_ROWS / 128), 256, gemm_smem>>>();
    topk_kernel     <<<N_ROWS, 256>>>();
    transpose_kernel<<<dim3(W_DIM / 32, D_DIM / 32), dim3(32, 8)>>>(Ad);
    rescore_kernel  <<<N_ROWS, 256>>>(x, Ae);
    decode_kernel   <<<N_ROWS, 256>>>(bd, out);
}